// round 4
// baseline (speedup 1.0000x reference)
#include <cuda_runtime.h>
#include <cstdint>

#define N_NODES 50000
#define N_EDGES 800000
#define IN_DIM 128
#define HIDDEN 256
#define N_CLASSES 16
#define N_GRAPHS 128

// ---------------- scratch (static device globals; no allocation) -------------
__device__ __align__(16) float g_bufA[(size_t)N_NODES * HIDDEN];
__device__ __align__(16) float g_bufB[(size_t)N_NODES * HIDDEN];
__device__ __align__(16) float g_bufC[(size_t)N_NODES * HIDDEN];
__device__ int   g_mode;                 // 1 = inputs are int64, 0 = int32
__device__ int   g_src[N_EDGES];
__device__ int   g_dst[N_EDGES];
__device__ int   g_batch[N_NODES];
__device__ float g_dinv[N_NODES];
__device__ int   g_degi[N_NODES];
__device__ int   g_rowptr[N_NODES];
__device__ int   g_cursor[N_NODES];
__device__ int   g_csr_src[N_EDGES];
__device__ float g_csr_nrm[N_EDGES];
__device__ float g_sums[N_GRAPHS * HIDDEN];
__device__ float g_cnt[N_GRAPHS];

// ---------------- dtype detection + normalization ----------------------------
// If edge_index is int64, values are 0..49999 so every odd int32 word is 0.
__global__ void detect_kernel(const void* __restrict__ ei_raw) {
    const int* p = (const int*)ei_raw;
    int m64 = 1;
    for (int i = 0; i < 128; i++) {
        if (p[2 * i + 1] != 0) { m64 = 0; break; }
    }
    g_mode = m64;
}

__global__ void convert_edges_kernel(const void* __restrict__ ei_raw) {
    int e = blockIdx.x * blockDim.x + threadIdx.x;
    if (e >= N_EDGES) return;
    if (g_mode) {
        const long long* q = (const long long*)ei_raw;
        g_src[e] = (int)q[e];
        g_dst[e] = (int)q[N_EDGES + e];
    } else {
        const int* q = (const int*)ei_raw;
        g_src[e] = q[e];
        g_dst[e] = q[N_EDGES + e];
    }
}

__global__ void convert_batch_kernel(const void* __restrict__ b_raw) {
    int i = blockIdx.x * blockDim.x + threadIdx.x;
    if (i >= N_NODES) return;
    if (g_mode) g_batch[i] = (int)((const long long*)b_raw)[i];
    else        g_batch[i] = ((const int*)b_raw)[i];
}

// ---------------- degree ----------------------------------------------------
__global__ void deg_init_kernel() {
    int i = blockIdx.x * blockDim.x + threadIdx.x;
    if (i < N_NODES) g_degi[i] = 0;
}

__global__ void deg_count_kernel() {
    int e = blockIdx.x * blockDim.x + threadIdx.x;
    if (e < N_EDGES) atomicAdd(&g_degi[g_dst[e]], 1);
}

__global__ void deg_finalize_kernel() {
    int i = blockIdx.x * blockDim.x + threadIdx.x;
    if (i < N_NODES) g_dinv[i] = rsqrtf((float)g_degi[i] + 1.0f);  // +1 self-loop
}

// ---------------- exclusive prefix scan over degrees (1 block) ---------------
__global__ __launch_bounds__(1024)
void scan_kernel() {
    __shared__ int partial[1024];
    const int tid = threadIdx.x;
    const int CH = (N_NODES + 1023) / 1024;     // 49
    const int start = tid * CH;
    int s = 0;
    for (int i = 0; i < CH; i++) {
        int idx = start + i;
        if (idx < N_NODES) s += g_degi[idx];
    }
    partial[tid] = s;
    __syncthreads();
    for (int d = 1; d < 1024; d <<= 1) {
        int v = 0;
        if (tid >= d) v = partial[tid - d];
        __syncthreads();
        if (tid >= d) partial[tid] += v;
        __syncthreads();
    }
    int run = (tid == 0) ? 0 : partial[tid - 1];
    for (int i = 0; i < CH; i++) {
        int idx = start + i;
        if (idx < N_NODES) {
            g_rowptr[idx] = run;
            g_cursor[idx] = run;
            run += g_degi[idx];
        }
    }
}

// ---------------- fill CSR: (src, norm) per edge, bucketed by dst ------------
__global__ void fill_kernel() {
    int e = blockIdx.x * blockDim.x + threadIdx.x;
    if (e >= N_EDGES) return;
    int src = g_src[e];
    int dst = g_dst[e];
    int pos = atomicAdd(&g_cursor[dst], 1);
    g_csr_src[pos] = src;
    g_csr_nrm[pos] = g_dinv[src] * g_dinv[dst];
}

// ---------------- SGEMM: C[N,256] = (relu?)A[N,K] @ W[K,256] (+bias) ---------
// srcSel: 0 = external A, 1 = g_bufA, 2 = g_bufC.  dstSel: 1 = g_bufA, 2 = g_bufB.
template<int K, bool RELU_IN>
__global__ __launch_bounds__(256)
void gemm_kernel(const float* __restrict__ Aext, int srcSel, int dstSel,
                 const float* __restrict__ W, const float* __restrict__ bias, int N) {
    const float* __restrict__ A = (srcSel == 0) ? Aext : (srcSel == 1 ? g_bufA : g_bufC);
    float* __restrict__ C = (dstSel == 1) ? g_bufA : g_bufB;

    __shared__ float As[16][132];
    __shared__ float Bs[16][128];

    const int tid = threadIdx.x;
    const int tx = tid & 15;
    const int ty = tid >> 4;
    const int rowBase = blockIdx.x * 128;
    const int colBase = blockIdx.y * 128;

    float acc[8][8];
#pragma unroll
    for (int i = 0; i < 8; i++)
#pragma unroll
        for (int j = 0; j < 8; j++) acc[i][j] = 0.0f;

    for (int k0 = 0; k0 < K; k0 += 16) {
#pragma unroll
        for (int it = 0; it < 2; it++) {
            int idx = tid + it * 256;
            int r   = idx >> 2;
            int k4  = (idx & 3) * 4;
            float4 v = make_float4(0.f, 0.f, 0.f, 0.f);
            int gr = rowBase + r;
            if (gr < N) v = *(const float4*)(A + (size_t)gr * K + k0 + k4);
            if (RELU_IN) {
                v.x = fmaxf(v.x, 0.f); v.y = fmaxf(v.y, 0.f);
                v.z = fmaxf(v.z, 0.f); v.w = fmaxf(v.w, 0.f);
            }
            As[k4 + 0][r] = v.x; As[k4 + 1][r] = v.y;
            As[k4 + 2][r] = v.z; As[k4 + 3][r] = v.w;
        }
#pragma unroll
        for (int it = 0; it < 2; it++) {
            int idx = tid + it * 256;
            int kr  = idx >> 5;
            int c4  = (idx & 31) * 4;
            *(float4*)&Bs[kr][c4] = *(const float4*)(W + (size_t)(k0 + kr) * HIDDEN + colBase + c4);
        }
        __syncthreads();

#pragma unroll
        for (int kk = 0; kk < 16; kk++) {
            float a[8], b[8];
#pragma unroll
            for (int j = 0; j < 8; j++) a[j] = As[kk][ty * 8 + j];
#pragma unroll
            for (int j = 0; j < 8; j++) b[j] = Bs[kk][tx * 8 + j];
#pragma unroll
            for (int i = 0; i < 8; i++)
#pragma unroll
                for (int j = 0; j < 8; j++) acc[i][j] += a[i] * b[j];
        }
        __syncthreads();
    }

#pragma unroll
    for (int i = 0; i < 8; i++) {
        int gr = rowBase + ty * 8 + i;
        if (gr >= N) continue;
#pragma unroll
        for (int j = 0; j < 8; j += 4) {
            int gc = colBase + tx * 8 + j;
            float4 v = make_float4(acc[i][j], acc[i][j + 1], acc[i][j + 2], acc[i][j + 3]);
            if (bias) {
                v.x += bias[gc];     v.y += bias[gc + 1];
                v.z += bias[gc + 2]; v.w += bias[gc + 3];
            }
            *(float4*)(C + (size_t)gr * HIDDEN + gc) = v;
        }
    }
}

// ---------------- CSR gather: out[n] = sum_in h[src]*norm + h[n]*dinv^2 + b --
// One 64-thread block per dst node; thread owns 4 consecutive columns.
// srcSel: 1 = g_bufA, 2 = g_bufB.  dstSel: 2 = g_bufB, 3 = g_bufC.
__global__ __launch_bounds__(64)
void gather_kernel(int srcSel, int dstSel, const float* __restrict__ bias) {
    const float* __restrict__ h = (srcSel == 1) ? g_bufA : g_bufB;
    float* __restrict__ out = (dstSel == 3) ? g_bufC : g_bufB;

    const int node = blockIdx.x;
    const int tid = threadIdx.x;
    const int c4 = tid * 4;

    __shared__ int   s_src[64];
    __shared__ float s_nrm[64];

    float d = g_dinv[node];
    float d2 = d * d;
    float4 self = *(const float4*)(h + (size_t)node * HIDDEN + c4);
    float4 bb   = *(const float4*)(bias + c4);
    float4 acc  = make_float4(self.x * d2 + bb.x, self.y * d2 + bb.y,
                              self.z * d2 + bb.z, self.w * d2 + bb.w);

    const int beg = g_rowptr[node];
    const int end = beg + g_degi[node];
    for (int off = beg; off < end; off += 64) {
        int i = off + tid;
        if (i < end) {
            s_src[tid] = g_csr_src[i];
            s_nrm[tid] = g_csr_nrm[i];
        }
        __syncthreads();
        int m = min(64, end - off);
#pragma unroll 2
        for (int j = 0; j < m; j++) {
            int s = s_src[j];
            float nm = s_nrm[j];
            float4 v = *(const float4*)(h + (size_t)s * HIDDEN + c4);
            acc.x += v.x * nm; acc.y += v.y * nm;
            acc.z += v.z * nm; acc.w += v.w * nm;
        }
        __syncthreads();
    }
    *(float4*)(out + (size_t)node * HIDDEN + c4) = acc;
}

// ---------------- pooling: one block per graph, binary search on sorted batch-
__global__ __launch_bounds__(256)
void pool_kernel() {
    __shared__ int s_lo, s_hi;
    const int g = blockIdx.x;
    if (threadIdx.x == 0) {
        int lo = 0, hi = N_NODES;
        while (lo < hi) { int mid = (lo + hi) >> 1; if (g_batch[mid] < g) lo = mid + 1; else hi = mid; }
        s_lo = lo;
        int lo2 = lo, hi2 = N_NODES;
        while (lo2 < hi2) { int mid = (lo2 + hi2) >> 1; if (g_batch[mid] < g + 1) lo2 = mid + 1; else hi2 = mid; }
        s_hi = lo2;
    }
    __syncthreads();
    const int c = threadIdx.x;
    const int lo = s_lo, hi = s_hi;
    float acc = 0.0f;
    for (int n = lo; n < hi; n++)
        acc += fmaxf(g_bufB[(size_t)n * HIDDEN + c], 0.0f);
    g_sums[g * HIDDEN + c] = acc;
    if (c == 0) g_cnt[g] = (float)(hi - lo);
}

// ---------------- output GEMM ------------------------------------------------
__global__ void out_kernel(const float* __restrict__ Wout, const float* __restrict__ bout,
                           float* __restrict__ out) {
    int idx = blockIdx.x * blockDim.x + threadIdx.x;
    if (idx >= N_GRAPHS * N_CLASSES) return;
    int g = idx / N_CLASSES;
    int c = idx % N_CLASSES;
    float inv = 1.0f / fmaxf(g_cnt[g], 1.0f);
    float acc = 0.0f;
#pragma unroll 8
    for (int k = 0; k < HIDDEN; k++)
        acc += g_sums[g * HIDDEN + k] * Wout[k * N_CLASSES + c];
    out[idx] = acc * inv + bout[c];
}

// ---------------- launch -----------------------------------------------------
extern "C" void kernel_launch(void* const* d_in, const int* in_sizes, int n_in,
                              void* d_out, int out_size) {
    const float* x    = (const float*)d_in[0];
    const void*  ei   = d_in[1];
    const void*  bat  = d_in[2];
    const float* W_in = (const float*)d_in[3];
    const float* b_in = (const float*)d_in[4];
    const float* W1   = (const float*)d_in[5];
    const float* b1   = (const float*)d_in[6];
    const float* W2   = (const float*)d_in[7];
    const float* b2   = (const float*)d_in[8];
    const float* Wout = (const float*)d_in[9];
    const float* bout = (const float*)d_in[10];
    float* out = (float*)d_out;

    const int TPB = 256;
    dim3 gemmGrid((N_NODES + 127) / 128, 2);

    // dtype normalize
    detect_kernel<<<1, 1>>>(ei);
    convert_edges_kernel<<<(N_EDGES + TPB - 1) / TPB, TPB>>>(ei);
    convert_batch_kernel<<<(N_NODES + TPB - 1) / TPB, TPB>>>(bat);

    // CSR build + dinv
    deg_init_kernel<<<(N_NODES + TPB - 1) / TPB, TPB>>>();
    deg_count_kernel<<<(N_EDGES + TPB - 1) / TPB, TPB>>>();
    scan_kernel<<<1, 1024>>>();
    deg_finalize_kernel<<<(N_NODES + TPB - 1) / TPB, TPB>>>();
    fill_kernel<<<(N_EDGES + TPB - 1) / TPB, TPB>>>();

    // h0 = x @ W_in + b_in  -> bufA
    gemm_kernel<IN_DIM, false><<<gemmGrid, TPB>>>(x, 0, 1, W_in, b_in, N_NODES);

    // layer 1: h1 = bufA @ W1 -> bufB; agg(+b1) -> bufC (pre-relu)
    gemm_kernel<HIDDEN, false><<<gemmGrid, TPB>>>(nullptr, 1, 2, W1, nullptr, N_NODES);
    gather_kernel<<<N_NODES, 64>>>(2, 3, b1);

    // layer 2: h2 = relu(bufC) @ W2 -> bufA; agg(+b2) -> bufB (pre-relu)
    gemm_kernel<HIDDEN, true><<<gemmGrid, TPB>>>(nullptr, 2, 1, W2, nullptr, N_NODES);
    gather_kernel<<<N_NODES, 64>>>(1, 2, b2);

    // pool (relu on read) + output GEMM
    pool_kernel<<<N_GRAPHS, TPB>>>();
    out_kernel<<<(N_GRAPHS * N_CLASSES + TPB - 1) / TPB, TPB>>>(Wout, bout, out);
}

// round 6
// speedup vs baseline: 1.3057x; 1.3057x over previous
#include <cuda_runtime.h>
#include <cuda_bf16.h>
#include <cstdint>

#define N_NODES 50000
#define N_PAD   50176
#define N_EDGES 800000
#define IN_DIM 128
#define HIDDEN 256
#define N_CLASSES 16
#define N_GRAPHS 128

// ---------------- scratch (static device globals; no allocation) -------------
__device__ __align__(16) float g_bufA[(size_t)N_NODES * HIDDEN];
__device__ __align__(16) float g_bufB[(size_t)N_NODES * HIDDEN];
__device__ __align__(16) float g_bufC[(size_t)N_NODES * HIDDEN];
__device__ __align__(16) __nv_bfloat16 g_ahi[(size_t)N_PAD * HIDDEN];
__device__ __align__(16) __nv_bfloat16 g_alo[(size_t)N_PAD * HIDDEN];
__device__ __align__(16) __nv_bfloat16 g_w0hi[HIDDEN * IN_DIM];   // W_in^T [256][128]
__device__ __align__(16) __nv_bfloat16 g_w0lo[HIDDEN * IN_DIM];
__device__ __align__(16) __nv_bfloat16 g_w1hi[HIDDEN * HIDDEN];   // W1^T [256][256]
__device__ __align__(16) __nv_bfloat16 g_w1lo[HIDDEN * HIDDEN];
__device__ __align__(16) __nv_bfloat16 g_w2hi[HIDDEN * HIDDEN];
__device__ __align__(16) __nv_bfloat16 g_w2lo[HIDDEN * HIDDEN];
__device__ int   g_mode;
__device__ int   g_src[N_EDGES];
__device__ int   g_dst[N_EDGES];
__device__ int   g_batch[N_NODES];
__device__ float g_dinv[N_NODES];
__device__ int   g_degi[N_NODES];
__device__ int   g_rowptr[N_NODES];
__device__ int   g_cursor[N_NODES];
__device__ int   g_csr_src[N_EDGES];
__device__ float g_csr_nrm[N_EDGES];
__device__ float g_sums[N_GRAPHS * HIDDEN];
__device__ float g_cnt[N_GRAPHS];

// ---------------- dtype detection + normalization ----------------------------
__global__ void detect_kernel(const void* __restrict__ ei_raw) {
    const int* p = (const int*)ei_raw;
    int m64 = 1;
    for (int i = 0; i < 128; i++)
        if (p[2 * i + 1] != 0) { m64 = 0; break; }
    g_mode = m64;
}
__global__ void convert_edges_kernel(const void* __restrict__ ei_raw) {
    int e = blockIdx.x * blockDim.x + threadIdx.x;
    if (e >= N_EDGES) return;
    if (g_mode) {
        const long long* q = (const long long*)ei_raw;
        g_src[e] = (int)q[e];
        g_dst[e] = (int)q[N_EDGES + e];
    } else {
        const int* q = (const int*)ei_raw;
        g_src[e] = q[e];
        g_dst[e] = q[N_EDGES + e];
    }
}
__global__ void convert_batch_kernel(const void* __restrict__ b_raw) {
    int i = blockIdx.x * blockDim.x + threadIdx.x;
    if (i >= N_NODES) return;
    if (g_mode) g_batch[i] = (int)((const long long*)b_raw)[i];
    else        g_batch[i] = ((const int*)b_raw)[i];
}

// ---------------- weight prep: transpose + bf16 hi/lo split -------------------
__global__ void prep_weights_kernel(const float* __restrict__ W0,
                                    const float* __restrict__ W1,
                                    const float* __restrict__ W2) {
    int idx = blockIdx.x * blockDim.x + threadIdx.x;
    const int S0 = HIDDEN * IN_DIM;
    const int S1 = HIDDEN * HIDDEN;
    float v; __nv_bfloat16 *ph, *pl; int off;
    if (idx < S0) {
        int n = idx >> 7, k = idx & 127;
        v = W0[k * HIDDEN + n]; ph = g_w0hi; pl = g_w0lo; off = n * IN_DIM + k;
    } else if (idx < S0 + S1) {
        int j = idx - S0; int n = j >> 8, k = j & 255;
        v = W1[k * HIDDEN + n]; ph = g_w1hi; pl = g_w1lo; off = n * HIDDEN + k;
    } else if (idx < S0 + 2 * S1) {
        int j = idx - S0 - S1; int n = j >> 8, k = j & 255;
        v = W2[k * HIDDEN + n]; ph = g_w2hi; pl = g_w2lo; off = n * HIDDEN + k;
    } else return;
    __nv_bfloat16 hi = __float2bfloat16(v);
    ph[off] = hi;
    pl[off] = __float2bfloat16(v - __bfloat162float(hi));
}

// ---------------- activation split: fp32 -> bf16 hi/lo ------------------------
// srcSel: 0 = ext, 1 = g_bufA, 2 = g_bufC
template<int K, bool RELU>
__global__ void convA_kernel(const float* __restrict__ ext, int srcSel) {
    const float* __restrict__ src = (srcSel == 0) ? ext : (srcSel == 1 ? g_bufA : g_bufC);
    long long idx = (long long)blockIdx.x * blockDim.x + threadIdx.x;
    if (idx >= (long long)N_NODES * K) return;
    float v = src[idx];
    if (RELU) v = fmaxf(v, 0.0f);
    __nv_bfloat16 hi = __float2bfloat16(v);
    g_ahi[idx] = hi;
    g_alo[idx] = __float2bfloat16(v - __bfloat162float(hi));
}

// ---------------- mma.sync helper ---------------------------------------------
__device__ __forceinline__ void mma16816(float* c, const uint32_t* a,
                                         uint32_t b0, uint32_t b1) {
    asm volatile(
        "mma.sync.aligned.m16n8k16.row.col.f32.bf16.bf16.f32 "
        "{%0,%1,%2,%3}, {%4,%5,%6,%7}, {%8,%9}, {%0,%1,%2,%3};"
        : "+f"(c[0]), "+f"(c[1]), "+f"(c[2]), "+f"(c[3])
        : "r"(a[0]), "r"(a[1]), "r"(a[2]), "r"(a[3]), "r"(b0), "r"(b1));
}

// smem: bf16 tiles 128 rows x 64 cols padded to 72 (144 B rows, conflict-free)
#define TROW 72
#define T_BYTES (128 * TROW * 2)       // 18432
#define AH_OFF 0
#define AL_OFF T_BYTES
#define BH_OFF (2 * T_BYTES)
#define BL_OFF (3 * T_BYTES)
#define SMEM_TOTAL (4 * T_BYTES)       // 73728

// ---------------- tensor-core GEMM: C[N,256] = A[N,K] @ W[K,256] (+bias) ------
// A as bf16 hi/lo [N_PAD][K]; W transposed bf16 hi/lo [256][K].
// Error-compensated: Ahi@Whi + Alo@Whi + Ahi@Wlo, fp32 accum.
// wSel: 0/1/2 -> W_in/W1/W2.  dstSel: 1 = g_bufA, 2 = g_bufB.
template<int K>
__global__ __launch_bounds__(256, 2)
void gemm_mma_kernel(int wSel, int dstSel, const float* __restrict__ bias) {
    extern __shared__ char smem[];
    const __nv_bfloat16* __restrict__ Wh =
        (wSel == 0) ? g_w0hi : (wSel == 1 ? g_w1hi : g_w2hi);
    const __nv_bfloat16* __restrict__ Wl =
        (wSel == 0) ? g_w0lo : (wSel == 1 ? g_w1lo : g_w2lo);
    float* __restrict__ C = (dstSel == 1) ? g_bufA : g_bufB;

    unsigned short* sAh = (unsigned short*)(smem + AH_OFF);
    unsigned short* sAl = (unsigned short*)(smem + AL_OFF);
    unsigned short* sBh = (unsigned short*)(smem + BH_OFF);
    unsigned short* sBl = (unsigned short*)(smem + BL_OFF);

    const int tid = threadIdx.x;
    const int wid = tid >> 5;
    const int lane = tid & 31;
    const int gid = lane >> 2;        // 0..7
    const int tig = lane & 3;         // 0..3
    const int rowBase = blockIdx.x * 128;
    const int colBase = blockIdx.y * 128;
    const int warp_m = (wid & 3) * 32;    // 4 warps along M
    const int warp_n = (wid >> 2) * 64;   // 2 warps along N

    float acc[2][8][4];
#pragma unroll
    for (int mt = 0; mt < 2; mt++)
#pragma unroll
        for (int nt = 0; nt < 8; nt++)
#pragma unroll
            for (int q = 0; q < 4; q++) acc[mt][nt][q] = 0.0f;

    const int NC = K / 64;
    for (int kc = 0; kc < NC; kc++) {
        const int k0 = kc * 64;
        // load A hi/lo tile: 128 rows x 64 bf16 = 1024 float4 per matrix
        for (int i = tid; i < 1024; i += 256) {
            int r = i >> 3, kg = (i & 7) * 8;
            size_t goff = (size_t)(rowBase + r) * K + k0 + kg;
            *(float4*)(sAh + r * TROW + kg) = *(const float4*)(g_ahi + goff);
            *(float4*)(sAl + r * TROW + kg) = *(const float4*)(g_alo + goff);
        }
        // load B hi/lo tile: 128 n-rows x 64 bf16
        for (int i = tid; i < 1024; i += 256) {
            int r = i >> 3, kg = (i & 7) * 8;
            size_t goff = (size_t)(colBase + r) * K + k0 + kg;
            *(float4*)(sBh + r * TROW + kg) = *(const float4*)(Wh + goff);
            *(float4*)(sBl + r * TROW + kg) = *(const float4*)(Wl + goff);
        }
        __syncthreads();

#pragma unroll
        for (int kk = 0; kk < 64; kk += 16) {
            // A fragments (hi and lo) for both 16-row tiles
            uint32_t ah[2][4], al[2][4];
#pragma unroll
            for (int mt = 0; mt < 2; mt++) {
                const unsigned short* base =
                    sAh + (warp_m + mt * 16 + gid) * TROW + kk + tig * 2;
                ah[mt][0] = *(const uint32_t*)(base);
                ah[mt][1] = *(const uint32_t*)(base + 8 * TROW);
                ah[mt][2] = *(const uint32_t*)(base + 8);
                ah[mt][3] = *(const uint32_t*)(base + 8 * TROW + 8);
                const unsigned short* basl =
                    sAl + (warp_m + mt * 16 + gid) * TROW + kk + tig * 2;
                al[mt][0] = *(const uint32_t*)(basl);
                al[mt][1] = *(const uint32_t*)(basl + 8 * TROW);
                al[mt][2] = *(const uint32_t*)(basl + 8);
                al[mt][3] = *(const uint32_t*)(basl + 8 * TROW + 8);
            }
#pragma unroll
            for (int nt = 0; nt < 8; nt++) {
                const unsigned short* bb =
                    sBh + (warp_n + nt * 8 + gid) * TROW + kk + tig * 2;
                uint32_t b0 = *(const uint32_t*)(bb);
                uint32_t b1 = *(const uint32_t*)(bb + 8);
                const unsigned short* bl =
                    sBl + (warp_n + nt * 8 + gid) * TROW + kk + tig * 2;
                uint32_t l0 = *(const uint32_t*)(bl);
                uint32_t l1 = *(const uint32_t*)(bl + 8);
#pragma unroll
                for (int mt = 0; mt < 2; mt++) {
                    mma16816(acc[mt][nt], ah[mt], b0, b1);   // Ahi @ Whi
                    mma16816(acc[mt][nt], al[mt], b0, b1);   // Alo @ Whi
                    mma16816(acc[mt][nt], ah[mt], l0, l1);   // Ahi @ Wlo
                }
            }
        }
        __syncthreads();
    }

    // epilogue: c0,c1 -> (row, col..col+1); c2,c3 -> (row+8, ...)
#pragma unroll
    for (int mt = 0; mt < 2; mt++) {
#pragma unroll
        for (int nt = 0; nt < 8; nt++) {
            int r0 = rowBase + warp_m + mt * 16 + gid;
            int cc = colBase + warp_n + nt * 8 + tig * 2;
            float bx = 0.f, by = 0.f;
            if (bias) { bx = bias[cc]; by = bias[cc + 1]; }
            if (r0 < N_NODES) {
                float2 v = make_float2(acc[mt][nt][0] + bx, acc[mt][nt][1] + by);
                *(float2*)(C + (size_t)r0 * HIDDEN + cc) = v;
            }
            if (r0 + 8 < N_NODES) {
                float2 v = make_float2(acc[mt][nt][2] + bx, acc[mt][nt][3] + by);
                *(float2*)(C + (size_t)(r0 + 8) * HIDDEN + cc) = v;
            }
        }
    }
}

// ---------------- degree / CSR ------------------------------------------------
__global__ void deg_init_kernel() {
    int i = blockIdx.x * blockDim.x + threadIdx.x;
    if (i < N_NODES) g_degi[i] = 0;
}
__global__ void deg_count_kernel() {
    int e = blockIdx.x * blockDim.x + threadIdx.x;
    if (e < N_EDGES) atomicAdd(&g_degi[g_dst[e]], 1);
}
__global__ void deg_finalize_kernel() {
    int i = blockIdx.x * blockDim.x + threadIdx.x;
    if (i < N_NODES) g_dinv[i] = rsqrtf((float)g_degi[i] + 1.0f);
}
__global__ __launch_bounds__(1024)
void scan_kernel() {
    __shared__ int partial[1024];
    const int tid = threadIdx.x;
    const int CH = (N_NODES + 1023) / 1024;
    const int start = tid * CH;
    int s = 0;
    for (int i = 0; i < CH; i++) {
        int idx = start + i;
        if (idx < N_NODES) s += g_degi[idx];
    }
    partial[tid] = s;
    __syncthreads();
    for (int d = 1; d < 1024; d <<= 1) {
        int v = 0;
        if (tid >= d) v = partial[tid - d];
        __syncthreads();
        if (tid >= d) partial[tid] += v;
        __syncthreads();
    }
    int run = (tid == 0) ? 0 : partial[tid - 1];
    for (int i = 0; i < CH; i++) {
        int idx = start + i;
        if (idx < N_NODES) {
            g_rowptr[idx] = run;
            g_cursor[idx] = run;
            run += g_degi[idx];
        }
    }
}
__global__ void fill_kernel() {
    int e = blockIdx.x * blockDim.x + threadIdx.x;
    if (e >= N_EDGES) return;
    int src = g_src[e];
    int dst = g_dst[e];
    int pos = atomicAdd(&g_cursor[dst], 1);
    g_csr_src[pos] = src;
    g_csr_nrm[pos] = g_dinv[src] * g_dinv[dst];
}

// ---------------- CSR gather --------------------------------------------------
// srcSel: 1 = g_bufA, 2 = g_bufB.  dstSel: 2 = g_bufB, 3 = g_bufC.
__global__ __launch_bounds__(64)
void gather_kernel(int srcSel, int dstSel, const float* __restrict__ bias) {
    const float* __restrict__ h = (srcSel == 1) ? g_bufA : g_bufB;
    float* __restrict__ out = (dstSel == 3) ? g_bufC : g_bufB;

    const int node = blockIdx.x;
    const int tid = threadIdx.x;
    const int c4 = tid * 4;

    __shared__ int   s_src[64];
    __shared__ float s_nrm[64];

    float d = g_dinv[node];
    float d2 = d * d;
    float4 self = *(const float4*)(h + (size_t)node * HIDDEN + c4);
    float4 bb   = *(const float4*)(bias + c4);
    float4 acc  = make_float4(self.x * d2 + bb.x, self.y * d2 + bb.y,
                              self.z * d2 + bb.z, self.w * d2 + bb.w);

    const int beg = g_rowptr[node];
    const int end = beg + g_degi[node];
    for (int off = beg; off < end; off += 64) {
        int i = off + tid;
        if (i < end) {
            s_src[tid] = g_csr_src[i];
            s_nrm[tid] = g_csr_nrm[i];
        }
        __syncthreads();
        int m = min(64, end - off);
#pragma unroll 2
        for (int j = 0; j < m; j++) {
            int s = s_src[j];
            float nm = s_nrm[j];
            float4 v = *(const float4*)(h + (size_t)s * HIDDEN + c4);
            acc.x += v.x * nm; acc.y += v.y * nm;
            acc.z += v.z * nm; acc.w += v.w * nm;
        }
        __syncthreads();
    }
    *(float4*)(out + (size_t)node * HIDDEN + c4) = acc;
}

// ---------------- pooling + output --------------------------------------------
__global__ __launch_bounds__(256)
void pool_kernel() {
    __shared__ int s_lo, s_hi;
    const int g = blockIdx.x;
    if (threadIdx.x == 0) {
        int lo = 0, hi = N_NODES;
        while (lo < hi) { int mid = (lo + hi) >> 1; if (g_batch[mid] < g) lo = mid + 1; else hi = mid; }
        s_lo = lo;
        int lo2 = lo, hi2 = N_NODES;
        while (lo2 < hi2) { int mid = (lo2 + hi2) >> 1; if (g_batch[mid] < g + 1) lo2 = mid + 1; else hi2 = mid; }
        s_hi = lo2;
    }
    __syncthreads();
    const int c = threadIdx.x;
    const int lo = s_lo, hi = s_hi;
    float acc = 0.0f;
    for (int n = lo; n < hi; n++)
        acc += fmaxf(g_bufB[(size_t)n * HIDDEN + c], 0.0f);
    g_sums[g * HIDDEN + c] = acc;
    if (c == 0) g_cnt[g] = (float)(hi - lo);
}
__global__ void out_kernel(const float* __restrict__ Wout, const float* __restrict__ bout,
                           float* __restrict__ out) {
    int idx = blockIdx.x * blockDim.x + threadIdx.x;
    if (idx >= N_GRAPHS * N_CLASSES) return;
    int g = idx / N_CLASSES;
    int c = idx % N_CLASSES;
    float inv = 1.0f / fmaxf(g_cnt[g], 1.0f);
    float acc = 0.0f;
#pragma unroll 8
    for (int k = 0; k < HIDDEN; k++)
        acc += g_sums[g * HIDDEN + k] * Wout[k * N_CLASSES + c];
    out[idx] = acc * inv + bout[c];
}

// ---------------- launch ------------------------------------------------------
extern "C" void kernel_launch(void* const* d_in, const int* in_sizes, int n_in,
                              void* d_out, int out_size) {
    const float* x    = (const float*)d_in[0];
    const void*  ei   = d_in[1];
    const void*  bat  = d_in[2];
    const float* W_in = (const float*)d_in[3];
    const float* b_in = (const float*)d_in[4];
    const float* W1   = (const float*)d_in[5];
    const float* b1   = (const float*)d_in[6];
    const float* W2   = (const float*)d_in[7];
    const float* b2   = (const float*)d_in[8];
    const float* Wout = (const float*)d_in[9];
    const float* bout = (const float*)d_in[10];
    float* out = (float*)d_out;

    const int TPB = 256;
    dim3 gemmGrid((N_NODES + 127) / 128, 2);   // 391 x 2

    cudaFuncSetAttribute(gemm_mma_kernel<IN_DIM>,
                         cudaFuncAttributeMaxDynamicSharedMemorySize, SMEM_TOTAL);
    cudaFuncSetAttribute(gemm_mma_kernel<HIDDEN>,
                         cudaFuncAttributeMaxDynamicSharedMemorySize, SMEM_TOTAL);

    // 1-3: dtype normalize
    detect_kernel<<<1, 1>>>(ei);
    convert_edges_kernel<<<(N_EDGES + TPB - 1) / TPB, TPB>>>(ei);
    convert_batch_kernel<<<(N_NODES + TPB - 1) / TPB, TPB>>>(bat);

    // 4-5: weight prep + x split
    prep_weights_kernel<<<(HIDDEN * IN_DIM + 2 * HIDDEN * HIDDEN + TPB - 1) / TPB, TPB>>>(W_in, W1, W2);
    convA_kernel<IN_DIM, false><<<(N_NODES * IN_DIM + TPB - 1) / TPB, TPB>>>(x, 0);

    // 6: h0 = x @ W_in + b_in -> bufA   [ncu-profiled launch]
    gemm_mma_kernel<IN_DIM><<<gemmGrid, TPB, SMEM_TOTAL>>>(0, 1, b_in);

    // 7-11: CSR build + dinv
    deg_init_kernel<<<(N_NODES + TPB - 1) / TPB, TPB>>>();
    deg_count_kernel<<<(N_EDGES + TPB - 1) / TPB, TPB>>>();
    scan_kernel<<<1, 1024>>>();
    deg_finalize_kernel<<<(N_NODES + TPB - 1) / TPB, TPB>>>();
    fill_kernel<<<(N_EDGES + TPB - 1) / TPB, TPB>>>();

    // layer 1: h1 = bufA @ W1 -> bufB; agg(+b1) -> bufC (pre-relu)
    convA_kernel<HIDDEN, false><<<(N_NODES * HIDDEN + TPB - 1) / TPB, TPB>>>(nullptr, 1);
    gemm_mma_kernel<HIDDEN><<<gemmGrid, TPB, SMEM_TOTAL>>>(1, 2, nullptr);
    gather_kernel<<<N_NODES, 64>>>(2, 3, b1);

    // layer 2: h2 = relu(bufC) @ W2 -> bufA; agg(+b2) -> bufB (pre-relu)
    convA_kernel<HIDDEN, true><<<(N_NODES * HIDDEN + TPB - 1) / TPB, TPB>>>(nullptr, 2);
    gemm_mma_kernel<HIDDEN><<<gemmGrid, TPB, SMEM_TOTAL>>>(2, 1, nullptr);
    gather_kernel<<<N_NODES, 64>>>(1, 2, b2);

    // pool (relu on read) + output GEMM
    pool_kernel<<<N_GRAPHS, TPB>>>();
    out_kernel<<<(N_GRAPHS * N_CLASSES + TPB - 1) / TPB, TPB>>>(Wout, bout, out);
}

// round 7
// speedup vs baseline: 1.4958x; 1.1456x over previous
#include <cuda_runtime.h>
#include <cuda_bf16.h>
#include <cstdint>

#define N_NODES 50000
#define N_EDGES 800000
#define IN_DIM 128
#define HIDDEN 256
#define N_CLASSES 16
#define N_GRAPHS 128

// ---------------- scratch (static device globals; no allocation) -------------
__device__ __align__(16) float g_bufA[(size_t)N_NODES * HIDDEN];
__device__ __align__(16) float g_bufB[(size_t)N_NODES * HIDDEN];
__device__ __align__(16) float g_bufC[(size_t)N_NODES * HIDDEN];
__device__ __align__(16) __nv_bfloat16 g_w0hi[HIDDEN * IN_DIM];   // W_in^T [256][128]
__device__ __align__(16) __nv_bfloat16 g_w0lo[HIDDEN * IN_DIM];
__device__ __align__(16) __nv_bfloat16 g_w1hi[HIDDEN * HIDDEN];   // W1^T [256][256]
__device__ __align__(16) __nv_bfloat16 g_w1lo[HIDDEN * HIDDEN];
__device__ __align__(16) __nv_bfloat16 g_w2hi[HIDDEN * HIDDEN];
__device__ __align__(16) __nv_bfloat16 g_w2lo[HIDDEN * HIDDEN];
__device__ int   g_mode;
__device__ int   g_src[N_EDGES];
__device__ int   g_dst[N_EDGES];
__device__ int   g_batch[N_NODES];
__device__ float g_dinv[N_NODES];
__device__ int   g_degi[N_NODES];
__device__ int   g_rowptr[N_NODES];
__device__ int   g_cursor[N_NODES];
__device__ int   g_csr_src[N_EDGES];
__device__ float g_csr_nrm[N_EDGES];
__device__ float g_sums[N_GRAPHS * HIDDEN];
__device__ float g_cnt[N_GRAPHS];

// ---------------- dtype detection + normalization ----------------------------
__global__ void detect_kernel(const void* __restrict__ ei_raw) {
    const int* p = (const int*)ei_raw;
    int m64 = 1;
    for (int i = 0; i < 128; i++)
        if (p[2 * i + 1] != 0) { m64 = 0; break; }
    g_mode = m64;
}
__global__ void convert_edges_kernel(const void* __restrict__ ei_raw) {
    int e = blockIdx.x * blockDim.x + threadIdx.x;
    if (e >= N_EDGES) return;
    if (g_mode) {
        const long long* q = (const long long*)ei_raw;
        g_src[e] = (int)q[e];
        g_dst[e] = (int)q[N_EDGES + e];
    } else {
        const int* q = (const int*)ei_raw;
        g_src[e] = q[e];
        g_dst[e] = q[N_EDGES + e];
    }
}
__global__ void convert_batch_kernel(const void* __restrict__ b_raw) {
    int i = blockIdx.x * blockDim.x + threadIdx.x;
    if (i >= N_NODES) return;
    if (g_mode) g_batch[i] = (int)((const long long*)b_raw)[i];
    else        g_batch[i] = ((const int*)b_raw)[i];
}

// ---------------- weight prep: transpose + bf16 hi/lo split -------------------
__global__ void prep_weights_kernel(const float* __restrict__ W0,
                                    const float* __restrict__ W1,
                                    const float* __restrict__ W2) {
    int idx = blockIdx.x * blockDim.x + threadIdx.x;
    const int S0 = HIDDEN * IN_DIM;
    const int S1 = HIDDEN * HIDDEN;
    float v; __nv_bfloat16 *ph, *pl; int off;
    if (idx < S0) {
        int n = idx >> 7, k = idx & 127;
        v = W0[k * HIDDEN + n]; ph = g_w0hi; pl = g_w0lo; off = n * IN_DIM + k;
    } else if (idx < S0 + S1) {
        int j = idx - S0; int n = j >> 8, k = j & 255;
        v = W1[k * HIDDEN + n]; ph = g_w1hi; pl = g_w1lo; off = n * HIDDEN + k;
    } else if (idx < S0 + 2 * S1) {
        int j = idx - S0 - S1; int n = j >> 8, k = j & 255;
        v = W2[k * HIDDEN + n]; ph = g_w2hi; pl = g_w2lo; off = n * HIDDEN + k;
    } else return;
    __nv_bfloat16 hi = __float2bfloat16(v);
    ph[off] = hi;
    pl[off] = __float2bfloat16(v - __bfloat162float(hi));
}

// ---------------- mma.sync helper ---------------------------------------------
__device__ __forceinline__ void mma16816(float* c, const uint32_t* a,
                                         uint32_t b0, uint32_t b1) {
    asm volatile(
        "mma.sync.aligned.m16n8k16.row.col.f32.bf16.bf16.f32 "
        "{%0,%1,%2,%3}, {%4,%5,%6,%7}, {%8,%9}, {%0,%1,%2,%3};"
        : "+f"(c[0]), "+f"(c[1]), "+f"(c[2]), "+f"(c[3])
        : "r"(a[0]), "r"(a[1]), "r"(a[2]), "r"(a[3]), "r"(b0), "r"(b1));
}

// smem: bf16 tiles 128 rows x 64 cols padded to 72 (144 B rows)
#define TROW 72
#define T_BYTES (128 * TROW * 2)       // 18432
#define AH_OFF 0
#define AL_OFF T_BYTES
#define BH_OFF (2 * T_BYTES)
#define BL_OFF (3 * T_BYTES)
#define SMEM_TOTAL (4 * T_BYTES)       // 73728

// ---------------- tensor-core GEMM: C[N,256] = split(A)[N,K] @ W[K,256] (+bias)
// A read as fp32 (optionally relu'd), split hi/lo inline in the smem loader.
// Error-compensated: Ahi@Whi + Alo@Whi + Ahi@Wlo, fp32 accum.
// srcSel: 0 = ext, 1 = g_bufA, 2 = g_bufC.  wSel: 0/1/2.  dstSel: 1=bufA, 2=bufB.
template<int K, bool RELU>
__global__ __launch_bounds__(256, 2)
void gemm_mma_kernel(const float* __restrict__ Aext, int srcSel,
                     int wSel, int dstSel, const float* __restrict__ bias) {
    extern __shared__ char smem[];
    const float* __restrict__ Afp =
        (srcSel == 0) ? Aext : (srcSel == 1 ? g_bufA : g_bufC);
    const __nv_bfloat16* __restrict__ Wh =
        (wSel == 0) ? g_w0hi : (wSel == 1 ? g_w1hi : g_w2hi);
    const __nv_bfloat16* __restrict__ Wl =
        (wSel == 0) ? g_w0lo : (wSel == 1 ? g_w1lo : g_w2lo);
    float* __restrict__ C = (dstSel == 1) ? g_bufA : g_bufB;

    unsigned short* sAh = (unsigned short*)(smem + AH_OFF);
    unsigned short* sAl = (unsigned short*)(smem + AL_OFF);
    unsigned short* sBh = (unsigned short*)(smem + BH_OFF);
    unsigned short* sBl = (unsigned short*)(smem + BL_OFF);

    const int tid = threadIdx.x;
    const int wid = tid >> 5;
    const int lane = tid & 31;
    const int gid = lane >> 2;        // 0..7
    const int tig = lane & 3;         // 0..3
    const int rowBase = blockIdx.x * 128;
    const int colBase = blockIdx.y * 128;
    const int warp_m = (wid & 3) * 32;    // 4 warps along M
    const int warp_n = (wid >> 2) * 64;   // 2 warps along N

    float acc[2][8][4];
#pragma unroll
    for (int mt = 0; mt < 2; mt++)
#pragma unroll
        for (int nt = 0; nt < 8; nt++)
#pragma unroll
            for (int q = 0; q < 4; q++) acc[mt][nt][q] = 0.0f;

    const int NC = K / 64;
    for (int kc = 0; kc < NC; kc++) {
        const int k0 = kc * 64;
        // A tile: 128 rows x 64 cols; read fp32, split hi/lo inline.
        for (int i = tid; i < 1024; i += 256) {
            int r = i >> 3, kg = (i & 7) * 8;
            int gr = rowBase + r;
            if (gr >= N_NODES) gr = N_NODES - 1;   // clamp: tail outputs masked at store
            const float* src = Afp + (size_t)gr * K + k0 + kg;
            float4 v0 = *(const float4*)src;
            float4 v1 = *(const float4*)(src + 4);
            float f[8] = {v0.x, v0.y, v0.z, v0.w, v1.x, v1.y, v1.z, v1.w};
            unsigned short hi[8], lo[8];
#pragma unroll
            for (int q = 0; q < 8; q++) {
                float v = RELU ? fmaxf(f[q], 0.0f) : f[q];
                __nv_bfloat16 h = __float2bfloat16(v);
                hi[q] = *(unsigned short*)&h;
                __nv_bfloat16 l = __float2bfloat16(v - __bfloat162float(h));
                lo[q] = *(unsigned short*)&l;
            }
            *(float4*)(sAh + r * TROW + kg) = *(float4*)hi;
            *(float4*)(sAl + r * TROW + kg) = *(float4*)lo;
        }
        // B tile: 128 n-rows x 64 bf16 (pre-split weights)
        for (int i = tid; i < 1024; i += 256) {
            int r = i >> 3, kg = (i & 7) * 8;
            size_t goff = (size_t)(colBase + r) * K + k0 + kg;
            *(float4*)(sBh + r * TROW + kg) = *(const float4*)(Wh + goff);
            *(float4*)(sBl + r * TROW + kg) = *(const float4*)(Wl + goff);
        }
        __syncthreads();

#pragma unroll
        for (int kk = 0; kk < 64; kk += 16) {
            uint32_t ah[2][4], al[2][4];
#pragma unroll
            for (int mt = 0; mt < 2; mt++) {
                const unsigned short* base =
                    sAh + (warp_m + mt * 16 + gid) * TROW + kk + tig * 2;
                ah[mt][0] = *(const uint32_t*)(base);
                ah[mt][1] = *(const uint32_t*)(base + 8 * TROW);
                ah[mt][2] = *(const uint32_t*)(base + 8);
                ah[mt][3] = *(const uint32_t*)(base + 8 * TROW + 8);
                const unsigned short* basl =
                    sAl + (warp_m + mt * 16 + gid) * TROW + kk + tig * 2;
                al[mt][0] = *(const uint32_t*)(basl);
                al[mt][1] = *(const uint32_t*)(basl + 8 * TROW);
                al[mt][2] = *(const uint32_t*)(basl + 8);
                al[mt][3] = *(const uint32_t*)(basl + 8 * TROW + 8);
            }
#pragma unroll
            for (int nt = 0; nt < 8; nt++) {
                const unsigned short* bb =
                    sBh + (warp_n + nt * 8 + gid) * TROW + kk + tig * 2;
                uint32_t b0 = *(const uint32_t*)(bb);
                uint32_t b1 = *(const uint32_t*)(bb + 8);
                const unsigned short* bl =
                    sBl + (warp_n + nt * 8 + gid) * TROW + kk + tig * 2;
                uint32_t l0 = *(const uint32_t*)(bl);
                uint32_t l1 = *(const uint32_t*)(bl + 8);
#pragma unroll
                for (int mt = 0; mt < 2; mt++) {
                    mma16816(acc[mt][nt], ah[mt], b0, b1);   // Ahi @ Whi
                    mma16816(acc[mt][nt], al[mt], b0, b1);   // Alo @ Whi
                    mma16816(acc[mt][nt], ah[mt], l0, l1);   // Ahi @ Wlo
                }
            }
        }
        __syncthreads();
    }

#pragma unroll
    for (int mt = 0; mt < 2; mt++) {
#pragma unroll
        for (int nt = 0; nt < 8; nt++) {
            int r0 = rowBase + warp_m + mt * 16 + gid;
            int cc = colBase + warp_n + nt * 8 + tig * 2;
            float bx = 0.f, by = 0.f;
            if (bias) { bx = bias[cc]; by = bias[cc + 1]; }
            if (r0 < N_NODES) {
                float2 v = make_float2(acc[mt][nt][0] + bx, acc[mt][nt][1] + by);
                *(float2*)(C + (size_t)r0 * HIDDEN + cc) = v;
            }
            if (r0 + 8 < N_NODES) {
                float2 v = make_float2(acc[mt][nt][2] + bx, acc[mt][nt][3] + by);
                *(float2*)(C + (size_t)(r0 + 8) * HIDDEN + cc) = v;
            }
        }
    }
}

// ---------------- degree / CSR ------------------------------------------------
__global__ void deg_init_kernel() {
    int i = blockIdx.x * blockDim.x + threadIdx.x;
    if (i < N_NODES) g_degi[i] = 0;
}
__global__ void deg_count_kernel() {
    int e = blockIdx.x * blockDim.x + threadIdx.x;
    if (e < N_EDGES) atomicAdd(&g_degi[g_dst[e]], 1);
}
__global__ void deg_finalize_kernel() {
    int i = blockIdx.x * blockDim.x + threadIdx.x;
    if (i < N_NODES) g_dinv[i] = rsqrtf((float)g_degi[i] + 1.0f);
}
__global__ __launch_bounds__(1024)
void scan_kernel() {
    __shared__ int partial[1024];
    const int tid = threadIdx.x;
    const int CH = (N_NODES + 1023) / 1024;
    const int start = tid * CH;
    int s = 0;
    for (int i = 0; i < CH; i++) {
        int idx = start + i;
        if (idx < N_NODES) s += g_degi[idx];
    }
    partial[tid] = s;
    __syncthreads();
    for (int d = 1; d < 1024; d <<= 1) {
        int v = 0;
        if (tid >= d) v = partial[tid - d];
        __syncthreads();
        if (tid >= d) partial[tid] += v;
        __syncthreads();
    }
    int run = (tid == 0) ? 0 : partial[tid - 1];
    for (int i = 0; i < CH; i++) {
        int idx = start + i;
        if (idx < N_NODES) {
            g_rowptr[idx] = run;
            g_cursor[idx] = run;
            run += g_degi[idx];
        }
    }
}
__global__ void fill_kernel() {
    int e = blockIdx.x * blockDim.x + threadIdx.x;
    if (e >= N_EDGES) return;
    int src = g_src[e];
    int dst = g_dst[e];
    int pos = atomicAdd(&g_cursor[dst], 1);
    g_csr_src[pos] = src;
    g_csr_nrm[pos] = g_dinv[src] * g_dinv[dst];
}

// ---------------- CSR gather --------------------------------------------------
// srcSel: 1 = g_bufA, 2 = g_bufB.  dstSel: 2 = g_bufB, 3 = g_bufC.
__global__ __launch_bounds__(64)
void gather_kernel(int srcSel, int dstSel, const float* __restrict__ bias) {
    const float* __restrict__ h = (srcSel == 1) ? g_bufA : g_bufB;
    float* __restrict__ out = (dstSel == 3) ? g_bufC : g_bufB;

    const int node = blockIdx.x;
    const int tid = threadIdx.x;
    const int c4 = tid * 4;

    __shared__ int   s_src[64];
    __shared__ float s_nrm[64];

    float d = g_dinv[node];
    float d2 = d * d;
    float4 self = *(const float4*)(h + (size_t)node * HIDDEN + c4);
    float4 bb   = *(const float4*)(bias + c4);
    float4 acc  = make_float4(self.x * d2 + bb.x, self.y * d2 + bb.y,
                              self.z * d2 + bb.z, self.w * d2 + bb.w);

    const int beg = g_rowptr[node];
    const int end = beg + g_degi[node];
    for (int off = beg; off < end; off += 64) {
        int i = off + tid;
        if (i < end) {
            s_src[tid] = g_csr_src[i];
            s_nrm[tid] = g_csr_nrm[i];
        }
        __syncthreads();
        int m = min(64, end - off);
#pragma unroll 2
        for (int j = 0; j < m; j++) {
            int s = s_src[j];
            float nm = s_nrm[j];
            float4 v = *(const float4*)(h + (size_t)s * HIDDEN + c4);
            acc.x += v.x * nm; acc.y += v.y * nm;
            acc.z += v.z * nm; acc.w += v.w * nm;
        }
        __syncthreads();
    }
    *(float4*)(out + (size_t)node * HIDDEN + c4) = acc;
}

// ---------------- pooling + output --------------------------------------------
__global__ __launch_bounds__(256)
void pool_kernel() {
    __shared__ int s_lo, s_hi;
    const int g = blockIdx.x;
    if (threadIdx.x == 0) {
        int lo = 0, hi = N_NODES;
        while (lo < hi) { int mid = (lo + hi) >> 1; if (g_batch[mid] < g) lo = mid + 1; else hi = mid; }
        s_lo = lo;
        int lo2 = lo, hi2 = N_NODES;
        while (lo2 < hi2) { int mid = (lo2 + hi2) >> 1; if (g_batch[mid] < g + 1) lo2 = mid + 1; else hi2 = mid; }
        s_hi = lo2;
    }
    __syncthreads();
    const int c = threadIdx.x;
    const int lo = s_lo, hi = s_hi;
    float acc = 0.0f;
    for (int n = lo; n < hi; n++)
        acc += fmaxf(g_bufB[(size_t)n * HIDDEN + c], 0.0f);
    g_sums[g * HIDDEN + c] = acc;
    if (c == 0) g_cnt[g] = (float)(hi - lo);
}
__global__ void out_kernel(const float* __restrict__ Wout, const float* __restrict__ bout,
                           float* __restrict__ out) {
    int idx = blockIdx.x * blockDim.x + threadIdx.x;
    if (idx >= N_GRAPHS * N_CLASSES) return;
    int g = idx / N_CLASSES;
    int c = idx % N_CLASSES;
    float inv = 1.0f / fmaxf(g_cnt[g], 1.0f);
    float acc = 0.0f;
#pragma unroll 8
    for (int k = 0; k < HIDDEN; k++)
        acc += g_sums[g * HIDDEN + k] * Wout[k * N_CLASSES + c];
    out[idx] = acc * inv + bout[c];
}

// ---------------- launch ------------------------------------------------------
extern "C" void kernel_launch(void* const* d_in, const int* in_sizes, int n_in,
                              void* d_out, int out_size) {
    const float* x    = (const float*)d_in[0];
    const void*  ei   = d_in[1];
    const void*  bat  = d_in[2];
    const float* W_in = (const float*)d_in[3];
    const float* b_in = (const float*)d_in[4];
    const float* W1   = (const float*)d_in[5];
    const float* b1   = (const float*)d_in[6];
    const float* W2   = (const float*)d_in[7];
    const float* b2   = (const float*)d_in[8];
    const float* Wout = (const float*)d_in[9];
    const float* bout = (const float*)d_in[10];
    float* out = (float*)d_out;

    const int TPB = 256;
    dim3 gemmGrid((N_NODES + 127) / 128, 2);   // 391 x 2

    cudaFuncSetAttribute(gemm_mma_kernel<IN_DIM, false>,
                         cudaFuncAttributeMaxDynamicSharedMemorySize, SMEM_TOTAL);
    cudaFuncSetAttribute(gemm_mma_kernel<HIDDEN, false>,
                         cudaFuncAttributeMaxDynamicSharedMemorySize, SMEM_TOTAL);
    cudaFuncSetAttribute(gemm_mma_kernel<HIDDEN, true>,
                         cudaFuncAttributeMaxDynamicSharedMemorySize, SMEM_TOTAL);

    // 1-4: dtype normalize + weight prep
    detect_kernel<<<1, 1>>>(ei);
    convert_edges_kernel<<<(N_EDGES + TPB - 1) / TPB, TPB>>>(ei);
    convert_batch_kernel<<<(N_NODES + TPB - 1) / TPB, TPB>>>(bat);
    prep_weights_kernel<<<(HIDDEN * IN_DIM + 2 * HIDDEN * HIDDEN + TPB - 1) / TPB, TPB>>>(W_in, W1, W2);

    // 5: h0 = x @ W_in + b_in -> bufA   [split fused in loader]
    gemm_mma_kernel<IN_DIM, false><<<gemmGrid, TPB, SMEM_TOTAL>>>(x, 0, 0, 1, b_in);

    // 6-10: CSR build + dinv
    deg_init_kernel<<<(N_NODES + TPB - 1) / TPB, TPB>>>();
    deg_count_kernel<<<(N_EDGES + TPB - 1) / TPB, TPB>>>();
    scan_kernel<<<1, 1024>>>();
    deg_finalize_kernel<<<(N_NODES + TPB - 1) / TPB, TPB>>>();
    fill_kernel<<<(N_EDGES + TPB - 1) / TPB, TPB>>>();

    // layer 1: h1 = bufA @ W1 -> bufB; agg(+b1) -> bufC (pre-relu)
    gemm_mma_kernel<HIDDEN, false><<<gemmGrid, TPB, SMEM_TOTAL>>>(nullptr, 1, 1, 2, nullptr);
    gather_kernel<<<N_NODES, 64>>>(2, 3, b1);

    // layer 2: h2 = relu(bufC) @ W2 -> bufA; agg(+b2) -> bufB (pre-relu)
    gemm_mma_kernel<HIDDEN, true><<<gemmGrid, TPB, SMEM_TOTAL>>>(nullptr, 2, 2, 1, nullptr);
    gather_kernel<<<N_NODES, 64>>>(1, 2, b2);

    // pool (relu on read) + output GEMM
    pool_kernel<<<N_GRAPHS, TPB>>>();
    out_kernel<<<(N_GRAPHS * N_CLASSES + TPB - 1) / TPB, TPB>>>(Wout, bout, out);
}

// round 8
// speedup vs baseline: 1.6842x; 1.1260x over previous
#include <cuda_runtime.h>
#include <cuda_bf16.h>
#include <cstdint>

#define N_NODES 50000
#define N_EDGES 800000
#define IN_DIM 128
#define HIDDEN 256
#define N_CLASSES 16
#define N_GRAPHS 128

// ---------------- scratch (static device globals; no allocation) -------------
__device__ __align__(16) float g_bufA[(size_t)N_NODES * HIDDEN];
__device__ __align__(16) float g_bufB[(size_t)N_NODES * HIDDEN];
__device__ __align__(16) float g_bufC[(size_t)N_NODES * HIDDEN];
__device__ __align__(16) __nv_bfloat16 g_wchi[HIDDEN * IN_DIM];   // (W_in@W1)^T [256][128]
__device__ __align__(16) __nv_bfloat16 g_wclo[HIDDEN * IN_DIM];
__device__ __align__(16) __nv_bfloat16 g_w2hi[HIDDEN * HIDDEN];   // W2^T [256][256]
__device__ __align__(16) __nv_bfloat16 g_w2lo[HIDDEN * HIDDEN];
__device__ float g_wb[HIDDEN];            // b_in @ W1
__device__ float g_coef[N_NODES];         // sum(norm) + dinv^2
__device__ int   g_mode;
__device__ int   g_src[N_EDGES];
__device__ int   g_dst[N_EDGES];
__device__ int   g_batch[N_NODES];
__device__ float g_dinv[N_NODES];
__device__ int   g_degi[N_NODES];
__device__ int   g_rowptr[N_NODES];
__device__ int   g_cursor[N_NODES];
__device__ int   g_csr_src[N_EDGES];
__device__ float g_csr_nrm[N_EDGES];
__device__ float g_sums[N_GRAPHS * HIDDEN];
__device__ float g_cnt[N_GRAPHS];

// ---------------- dtype detection + normalization ----------------------------
__global__ void detect_kernel(const void* __restrict__ ei_raw) {
    const int* p = (const int*)ei_raw;
    int m64 = 1;
    for (int i = 0; i < 128; i++)
        if (p[2 * i + 1] != 0) { m64 = 0; break; }
    g_mode = m64;
}
// also zeroes the degree array (fused deg_init)
__global__ void convert_edges_kernel(const void* __restrict__ ei_raw) {
    int e = blockIdx.x * blockDim.x + threadIdx.x;
    if (e < N_NODES) g_degi[e] = 0;
    if (e >= N_EDGES) return;
    if (g_mode) {
        const long long* q = (const long long*)ei_raw;
        g_src[e] = (int)q[e];
        g_dst[e] = (int)q[N_EDGES + e];
    } else {
        const int* q = (const int*)ei_raw;
        g_src[e] = q[e];
        g_dst[e] = q[N_EDGES + e];
    }
}
__global__ void convert_batch_kernel(const void* __restrict__ b_raw) {
    int i = blockIdx.x * blockDim.x + threadIdx.x;
    if (i >= N_NODES) return;
    if (g_mode) g_batch[i] = (int)((const long long*)b_raw)[i];
    else        g_batch[i] = ((const int*)b_raw)[i];
}

// ---------------- degree count -----------------------------------------------
__global__ void deg_count_kernel() {
    int e = blockIdx.x * blockDim.x + threadIdx.x;
    if (e < N_EDGES) atomicAdd(&g_degi[g_dst[e]], 1);
}

// ---------------- exclusive scan over degrees + dinv (1 block) ----------------
__global__ __launch_bounds__(1024)
void scan_kernel() {
    __shared__ int partial[1024];
    const int tid = threadIdx.x;
    const int CH = (N_NODES + 1023) / 1024;
    const int start = tid * CH;
    int s = 0;
    for (int i = 0; i < CH; i++) {
        int idx = start + i;
        if (idx < N_NODES) s += g_degi[idx];
    }
    partial[tid] = s;
    __syncthreads();
    for (int d = 1; d < 1024; d <<= 1) {
        int v = 0;
        if (tid >= d) v = partial[tid - d];
        __syncthreads();
        if (tid >= d) partial[tid] += v;
        __syncthreads();
    }
    int run = (tid == 0) ? 0 : partial[tid - 1];
    for (int i = 0; i < CH; i++) {
        int idx = start + i;
        if (idx < N_NODES) {
            int dg = g_degi[idx];
            g_rowptr[idx] = run;
            g_cursor[idx] = run;
            g_dinv[idx]   = rsqrtf((float)dg + 1.0f);   // +1 self-loop
            run += dg;
        }
    }
}
__global__ void fill_kernel() {
    int e = blockIdx.x * blockDim.x + threadIdx.x;
    if (e >= N_EDGES) return;
    int src = g_src[e];
    int dst = g_dst[e];
    int pos = atomicAdd(&g_cursor[dst], 1);
    g_csr_src[pos] = src;
    g_csr_nrm[pos] = g_dinv[src] * g_dinv[dst];
}

// ---------------- combine: Wc = W_in@W1 (split hi/lo, transposed), wb = b_in@W1
__global__ __launch_bounds__(256)
void combine_kernel(const float* __restrict__ W0, const float* __restrict__ W1,
                    const float* __restrict__ b_in) {
    const int j = threadIdx.x;          // 0..255 output column
    const int p = blockIdx.x;           // 0..127 = Wc row, 128 = wb
    float acc = 0.0f;
    if (p < IN_DIM) {
#pragma unroll 8
        for (int k = 0; k < HIDDEN; k++)
            acc += W0[p * HIDDEN + k] * W1[k * HIDDEN + j];
        __nv_bfloat16 hi = __float2bfloat16(acc);
        g_wchi[j * IN_DIM + p] = hi;
        g_wclo[j * IN_DIM + p] = __float2bfloat16(acc - __bfloat162float(hi));
    } else {
#pragma unroll 8
        for (int k = 0; k < HIDDEN; k++)
            acc += b_in[k] * W1[k * HIDDEN + j];
        g_wb[j] = acc;
    }
}

// ---------------- W2 prep: transpose + bf16 hi/lo split ------------------------
__global__ void prep_w2_kernel(const float* __restrict__ W2) {
    int idx = blockIdx.x * blockDim.x + threadIdx.x;
    if (idx >= HIDDEN * HIDDEN) return;
    int n = idx >> 8, k = idx & 255;
    float v = W2[k * HIDDEN + n];
    __nv_bfloat16 hi = __float2bfloat16(v);
    g_w2hi[n * HIDDEN + k] = hi;
    g_w2lo[n * HIDDEN + k] = __float2bfloat16(v - __bfloat162float(hi));
}

// ---------------- CSR gather: out[n] = sum h[src]*norm + h[n]*dinv^2 ----------
// DIM = 128 (x, writes coef) or 256. RELU applied to h on read.
// srcSel: 0 = ext, 1 = g_bufA.  dstSel: 2 = g_bufB, 3 = g_bufC.
template<int DIM, bool RELU, bool COEF>
__global__ __launch_bounds__(64)
void gather_kernel(const float* __restrict__ ext, int srcSel, int dstSel) {
    const float* __restrict__ h = (srcSel == 0) ? ext : g_bufA;
    float* __restrict__ out = (dstSel == 2) ? g_bufB : g_bufC;

    const int node = blockIdx.x;
    const int tid = threadIdx.x;

    __shared__ int   s_src[64];
    __shared__ float s_nrm[64];

    const float d = g_dinv[node];
    const float d2 = d * d;
    const int beg = g_rowptr[node];
    const int end = beg + g_degi[node];
    float ssum = 0.0f;

    if (DIM == 128) {
        const int c2 = tid * 2;
        float2 self = *(const float2*)(h + (size_t)node * DIM + c2);
        if (RELU) { self.x = fmaxf(self.x, 0.f); self.y = fmaxf(self.y, 0.f); }
        float2 acc = make_float2(self.x * d2, self.y * d2);
        for (int off = beg; off < end; off += 64) {
            int i = off + tid;
            if (i < end) { s_src[tid] = g_csr_src[i]; s_nrm[tid] = g_csr_nrm[i]; }
            __syncthreads();
            int m = min(64, end - off);
#pragma unroll 2
            for (int j = 0; j < m; j++) {
                int s = s_src[j];
                float nm = s_nrm[j];
                ssum += nm;
                float2 v = *(const float2*)(h + (size_t)s * DIM + c2);
                if (RELU) { v.x = fmaxf(v.x, 0.f); v.y = fmaxf(v.y, 0.f); }
                acc.x += v.x * nm; acc.y += v.y * nm;
            }
            __syncthreads();
        }
        *(float2*)(out + (size_t)node * DIM + c2) = acc;
    } else {
        const int c4 = tid * 4;
        float4 self = *(const float4*)(h + (size_t)node * DIM + c4);
        if (RELU) {
            self.x = fmaxf(self.x, 0.f); self.y = fmaxf(self.y, 0.f);
            self.z = fmaxf(self.z, 0.f); self.w = fmaxf(self.w, 0.f);
        }
        float4 acc = make_float4(self.x * d2, self.y * d2, self.z * d2, self.w * d2);
        for (int off = beg; off < end; off += 64) {
            int i = off + tid;
            if (i < end) { s_src[tid] = g_csr_src[i]; s_nrm[tid] = g_csr_nrm[i]; }
            __syncthreads();
            int m = min(64, end - off);
#pragma unroll 2
            for (int j = 0; j < m; j++) {
                int s = s_src[j];
                float nm = s_nrm[j];
                ssum += nm;
                float4 v = *(const float4*)(h + (size_t)s * DIM + c4);
                if (RELU) {
                    v.x = fmaxf(v.x, 0.f); v.y = fmaxf(v.y, 0.f);
                    v.z = fmaxf(v.z, 0.f); v.w = fmaxf(v.w, 0.f);
                }
                acc.x += v.x * nm; acc.y += v.y * nm;
                acc.z += v.z * nm; acc.w += v.w * nm;
            }
            __syncthreads();
        }
        *(float4*)(out + (size_t)node * DIM + c4) = acc;
    }
    if (COEF && tid == 0) g_coef[node] = ssum + d2;
}

// ---------------- mma.sync helper ---------------------------------------------
__device__ __forceinline__ void mma16816(float* c, const uint32_t* a,
                                         uint32_t b0, uint32_t b1) {
    asm volatile(
        "mma.sync.aligned.m16n8k16.row.col.f32.bf16.bf16.f32 "
        "{%0,%1,%2,%3}, {%4,%5,%6,%7}, {%8,%9}, {%0,%1,%2,%3};"
        : "+f"(c[0]), "+f"(c[1]), "+f"(c[2]), "+f"(c[3])
        : "r"(a[0]), "r"(a[1]), "r"(a[2]), "r"(a[3]), "r"(b0), "r"(b1));
}

#define TROW 72
#define T_BYTES (128 * TROW * 2)
#define AH_OFF 0
#define AL_OFF T_BYTES
#define BH_OFF (2 * T_BYTES)
#define BL_OFF (3 * T_BYTES)
#define SMEM_TOTAL (4 * T_BYTES)       // 73728

// ---------------- tensor-core GEMM: C[N,256] = split(A)[N,K] @ W[K,256] -------
// Error-compensated 3-pass bf16. Epilogue: + bias[c] (+ coef[r]*wb[c] if useWb).
// srcSel: 1 = g_bufC (v), 2 = g_bufB.  wSel: 0 = Wc, 1 = W2.  dstSel: 1=bufA, 3=bufC.
template<int K>
__global__ __launch_bounds__(256, 2)
void gemm_mma_kernel(int srcSel, int wSel, int dstSel,
                     const float* __restrict__ bias, int useWb) {
    extern __shared__ char smem[];
    const float* __restrict__ Afp = (srcSel == 1) ? g_bufC : g_bufB;
    const __nv_bfloat16* __restrict__ Wh = (wSel == 0) ? g_wchi : g_w2hi;
    const __nv_bfloat16* __restrict__ Wl = (wSel == 0) ? g_wclo : g_w2lo;
    float* __restrict__ C = (dstSel == 1) ? g_bufA : g_bufC;

    unsigned short* sAh = (unsigned short*)(smem + AH_OFF);
    unsigned short* sAl = (unsigned short*)(smem + AL_OFF);
    unsigned short* sBh = (unsigned short*)(smem + BH_OFF);
    unsigned short* sBl = (unsigned short*)(smem + BL_OFF);

    const int tid = threadIdx.x;
    const int wid = tid >> 5;
    const int lane = tid & 31;
    const int gid = lane >> 2;
    const int tig = lane & 3;
    const int rowBase = blockIdx.x * 128;
    const int colBase = blockIdx.y * 128;
    const int warp_m = (wid & 3) * 32;
    const int warp_n = (wid >> 2) * 64;

    float acc[2][8][4];
#pragma unroll
    for (int mt = 0; mt < 2; mt++)
#pragma unroll
        for (int nt = 0; nt < 8; nt++)
#pragma unroll
            for (int q = 0; q < 4; q++) acc[mt][nt][q] = 0.0f;

    const int NC = K / 64;
    for (int kc = 0; kc < NC; kc++) {
        const int k0 = kc * 64;
        for (int i = tid; i < 1024; i += 256) {
            int r = i >> 3, kg = (i & 7) * 8;
            int gr = rowBase + r;
            if (gr >= N_NODES) gr = N_NODES - 1;   // clamp; tail masked at store
            const float* src = Afp + (size_t)gr * K + k0 + kg;
            float4 v0 = *(const float4*)src;
            float4 v1 = *(const float4*)(src + 4);
            float f[8] = {v0.x, v0.y, v0.z, v0.w, v1.x, v1.y, v1.z, v1.w};
            unsigned short hi[8], lo[8];
#pragma unroll
            for (int q = 0; q < 8; q++) {
                __nv_bfloat16 h = __float2bfloat16(f[q]);
                hi[q] = *(unsigned short*)&h;
                __nv_bfloat16 l = __float2bfloat16(f[q] - __bfloat162float(h));
                lo[q] = *(unsigned short*)&l;
            }
            *(float4*)(sAh + r * TROW + kg) = *(float4*)hi;
            *(float4*)(sAl + r * TROW + kg) = *(float4*)lo;
        }
        for (int i = tid; i < 1024; i += 256) {
            int r = i >> 3, kg = (i & 7) * 8;
            size_t goff = (size_t)(colBase + r) * K + k0 + kg;
            *(float4*)(sBh + r * TROW + kg) = *(const float4*)(Wh + goff);
            *(float4*)(sBl + r * TROW + kg) = *(const float4*)(Wl + goff);
        }
        __syncthreads();

#pragma unroll
        for (int kk = 0; kk < 64; kk += 16) {
            uint32_t ah[2][4], al[2][4];
#pragma unroll
            for (int mt = 0; mt < 2; mt++) {
                const unsigned short* base =
                    sAh + (warp_m + mt * 16 + gid) * TROW + kk + tig * 2;
                ah[mt][0] = *(const uint32_t*)(base);
                ah[mt][1] = *(const uint32_t*)(base + 8 * TROW);
                ah[mt][2] = *(const uint32_t*)(base + 8);
                ah[mt][3] = *(const uint32_t*)(base + 8 * TROW + 8);
                const unsigned short* basl =
                    sAl + (warp_m + mt * 16 + gid) * TROW + kk + tig * 2;
                al[mt][0] = *(const uint32_t*)(basl);
                al[mt][1] = *(const uint32_t*)(basl + 8 * TROW);
                al[mt][2] = *(const uint32_t*)(basl + 8);
                al[mt][3] = *(const uint32_t*)(basl + 8 * TROW + 8);
            }
#pragma unroll
            for (int nt = 0; nt < 8; nt++) {
                const unsigned short* bb =
                    sBh + (warp_n + nt * 8 + gid) * TROW + kk + tig * 2;
                uint32_t b0 = *(const uint32_t*)(bb);
                uint32_t b1 = *(const uint32_t*)(bb + 8);
                const unsigned short* bl =
                    sBl + (warp_n + nt * 8 + gid) * TROW + kk + tig * 2;
                uint32_t l0 = *(const uint32_t*)(bl);
                uint32_t l1 = *(const uint32_t*)(bl + 8);
#pragma unroll
                for (int mt = 0; mt < 2; mt++) {
                    mma16816(acc[mt][nt], ah[mt], b0, b1);   // Ahi @ Whi
                    mma16816(acc[mt][nt], al[mt], b0, b1);   // Alo @ Whi
                    mma16816(acc[mt][nt], ah[mt], l0, l1);   // Ahi @ Wlo
                }
            }
        }
        __syncthreads();
    }

#pragma unroll
    for (int mt = 0; mt < 2; mt++) {
#pragma unroll
        for (int nt = 0; nt < 8; nt++) {
            int r0 = rowBase + warp_m + mt * 16 + gid;
            int cc = colBase + warp_n + nt * 8 + tig * 2;
            float bx = bias[cc], by = bias[cc + 1];
            float w0 = 0.f, w1v = 0.f;
            if (useWb) { w0 = g_wb[cc]; w1v = g_wb[cc + 1]; }
            if (r0 < N_NODES) {
                float cf = useWb ? g_coef[r0] : 0.f;
                float2 v = make_float2(acc[mt][nt][0] + bx + cf * w0,
                                       acc[mt][nt][1] + by + cf * w1v);
                *(float2*)(C + (size_t)r0 * HIDDEN + cc) = v;
            }
            if (r0 + 8 < N_NODES) {
                float cf = useWb ? g_coef[r0 + 8] : 0.f;
                float2 v = make_float2(acc[mt][nt][2] + bx + cf * w0,
                                       acc[mt][nt][3] + by + cf * w1v);
                *(float2*)(C + (size_t)(r0 + 8) * HIDDEN + cc) = v;
            }
        }
    }
}

// ---------------- pooling + output --------------------------------------------
// reads relu(g_bufC)
__global__ __launch_bounds__(256)
void pool_kernel() {
    __shared__ int s_lo, s_hi;
    const int g = blockIdx.x;
    if (threadIdx.x == 0) {
        int lo = 0, hi = N_NODES;
        while (lo < hi) { int mid = (lo + hi) >> 1; if (g_batch[mid] < g) lo = mid + 1; else hi = mid; }
        s_lo = lo;
        int lo2 = lo, hi2 = N_NODES;
        while (lo2 < hi2) { int mid = (lo2 + hi2) >> 1; if (g_batch[mid] < g + 1) lo2 = mid + 1; else hi2 = mid; }
        s_hi = lo2;
    }
    __syncthreads();
    const int c = threadIdx.x;
    const int lo = s_lo, hi = s_hi;
    float acc = 0.0f;
    for (int n = lo; n < hi; n++)
        acc += fmaxf(g_bufC[(size_t)n * HIDDEN + c], 0.0f);
    g_sums[g * HIDDEN + c] = acc;
    if (c == 0) g_cnt[g] = (float)(hi - lo);
}
__global__ void out_kernel(const float* __restrict__ Wout, const float* __restrict__ bout,
                           float* __restrict__ out) {
    int idx = blockIdx.x * blockDim.x + threadIdx.x;
    if (idx >= N_GRAPHS * N_CLASSES) return;
    int g = idx / N_CLASSES;
    int c = idx % N_CLASSES;
    float inv = 1.0f / fmaxf(g_cnt[g], 1.0f);
    float acc = 0.0f;
#pragma unroll 8
    for (int k = 0; k < HIDDEN; k++)
        acc += g_sums[g * HIDDEN + k] * Wout[k * N_CLASSES + c];
    out[idx] = acc * inv + bout[c];
}

// ---------------- launch ------------------------------------------------------
extern "C" void kernel_launch(void* const* d_in, const int* in_sizes, int n_in,
                              void* d_out, int out_size) {
    const float* x    = (const float*)d_in[0];
    const void*  ei   = d_in[1];
    const void*  bat  = d_in[2];
    const float* W_in = (const float*)d_in[3];
    const float* b_in = (const float*)d_in[4];
    const float* W1   = (const float*)d_in[5];
    const float* b1   = (const float*)d_in[6];
    const float* W2   = (const float*)d_in[7];
    const float* b2   = (const float*)d_in[8];
    const float* Wout = (const float*)d_in[9];
    const float* bout = (const float*)d_in[10];
    float* out = (float*)d_out;

    const int TPB = 256;
    dim3 gemmGrid((N_NODES + 127) / 128, 2);   // 391 x 2

    cudaFuncSetAttribute(gemm_mma_kernel<IN_DIM>,
                         cudaFuncAttributeMaxDynamicSharedMemorySize, SMEM_TOTAL);
    cudaFuncSetAttribute(gemm_mma_kernel<HIDDEN>,
                         cudaFuncAttributeMaxDynamicSharedMemorySize, SMEM_TOTAL);

    // 1-3: dtype normalize (+deg zero fused into #2)
    detect_kernel<<<1, 1>>>(ei);
    convert_edges_kernel<<<(N_EDGES + TPB - 1) / TPB, TPB>>>(ei);
    convert_batch_kernel<<<(N_NODES + TPB - 1) / TPB, TPB>>>(bat);

    // 4-6: CSR build (scan also computes dinv)
    deg_count_kernel<<<(N_EDGES + TPB - 1) / TPB, TPB>>>();
    scan_kernel<<<1, 1024>>>();
    fill_kernel<<<(N_EDGES + TPB - 1) / TPB, TPB>>>();

    // 7-8: weight prep (Wc = W_in@W1, wb = b_in@W1; W2 split)
    combine_kernel<<<IN_DIM + 1, 256>>>(W_in, W1, b_in);
    prep_w2_kernel<<<(HIDDEN * HIDDEN + TPB - 1) / TPB, TPB>>>(W2);

    // 9: v = M(x) (128-dim gather) -> bufC, coef
    gather_kernel<IN_DIM, false, true><<<N_NODES, 64>>>(x, 0, 3);

    // 10: C1 = v@Wc + coef*wb + b1 -> bufA   (layer-1 fused GEMM, K=128)
    gemm_mma_kernel<IN_DIM><<<gemmGrid, TPB, SMEM_TOTAL>>>(1, 0, 1, b1, 1);

    // 11: M(relu(C1)) (256-dim gather w/ relu) -> bufB
    gather_kernel<HIDDEN, true, false><<<N_NODES, 64>>>(nullptr, 1, 2);

    // 12: C2 = M@W2 + b2 -> bufC   (layer-2 GEMM, K=256)
    gemm_mma_kernel<HIDDEN><<<gemmGrid, TPB, SMEM_TOTAL>>>(2, 1, 3, b2, 0);

    // 13-14: pool (relu on read) + output GEMM
    pool_kernel<<<N_GRAPHS, TPB>>>();
    out_kernel<<<(N_GRAPHS * N_CLASSES + TPB - 1) / TPB, TPB>>>(Wout, bout, out);
}

// round 9
// speedup vs baseline: 2.1252x; 1.2619x over previous
#include <cuda_runtime.h>
#include <cuda_bf16.h>
#include <cstdint>

#define N_NODES 50000
#define N_EDGES 800000
#define IN_DIM 128
#define HIDDEN 256
#define N_CLASSES 16
#define N_GRAPHS 128
#define NB_SCAN ((N_NODES + 255) / 256)   // 196

// ---------------- scratch (static device globals; no allocation) -------------
__device__ __align__(16) float g_bufA[(size_t)N_NODES * HIDDEN];
__device__ __align__(16) float g_bufB[(size_t)N_NODES * HIDDEN];
__device__ __align__(16) float g_bufC[(size_t)N_NODES * HIDDEN];
__device__ __align__(16) __nv_bfloat16 g_wchi[HIDDEN * IN_DIM];   // (W_in@W1)^T
__device__ __align__(16) __nv_bfloat16 g_wclo[HIDDEN * IN_DIM];
__device__ __align__(16) __nv_bfloat16 g_w2hi[HIDDEN * HIDDEN];   // W2^T
__device__ __align__(16) __nv_bfloat16 g_w2lo[HIDDEN * HIDDEN];
__device__ float g_wb[HIDDEN];            // b_in @ W1
__device__ float g_coef[N_NODES];         // sum(norm) + dinv^2
__device__ int   g_mode;
__device__ int   g_src[N_EDGES];
__device__ int   g_dst[N_EDGES];
__device__ int   g_batch[N_NODES];
__device__ float g_dinv[N_NODES];
__device__ int   g_degi[N_NODES];
__device__ int   g_rowptr[N_NODES];
__device__ int   g_cursor[N_NODES];
__device__ int   g_part[256];
__device__ int   g_csr_src[N_EDGES];
__device__ float g_csr_nrm[N_EDGES];

// ---------------- dtype detection + normalization ----------------------------
__global__ void detect_kernel(const void* __restrict__ ei_raw) {
    const int* p = (const int*)ei_raw;
    int m64 = 1;
    for (int i = 0; i < 128; i++)
        if (p[2 * i + 1] != 0) { m64 = 0; break; }
    g_mode = m64;
}
// converts batch AND zeroes degree array (must run before convert_edges)
__global__ void convert_batch_kernel(const void* __restrict__ b_raw) {
    int i = blockIdx.x * blockDim.x + threadIdx.x;
    if (i >= N_NODES) return;
    g_degi[i] = 0;
    if (g_mode) g_batch[i] = (int)((const long long*)b_raw)[i];
    else        g_batch[i] = ((const int*)b_raw)[i];
}
// converts edges AND counts degrees (fused deg_count)
__global__ void convert_edges_kernel(const void* __restrict__ ei_raw) {
    int e = blockIdx.x * blockDim.x + threadIdx.x;
    if (e >= N_EDGES) return;
    int s, d;
    if (g_mode) {
        const long long* q = (const long long*)ei_raw;
        s = (int)q[e];
        d = (int)q[N_EDGES + e];
    } else {
        const int* q = (const int*)ei_raw;
        s = q[e];
        d = q[N_EDGES + e];
    }
    g_src[e] = s;
    g_dst[e] = d;
    atomicAdd(&g_degi[d], 1);
}

// ---------------- 3-phase exclusive scan over degrees -------------------------
__global__ __launch_bounds__(256) void scan1_kernel() {
    __shared__ int sh[256];
    int idx = blockIdx.x * 256 + threadIdx.x;
    sh[threadIdx.x] = (idx < N_NODES) ? g_degi[idx] : 0;
    __syncthreads();
    for (int d = 128; d > 0; d >>= 1) {
        if (threadIdx.x < d) sh[threadIdx.x] += sh[threadIdx.x + d];
        __syncthreads();
    }
    if (threadIdx.x == 0) g_part[blockIdx.x] = sh[0];
}
__global__ __launch_bounds__(256) void scan2_kernel() {
    __shared__ int sh[256];
    int t = threadIdx.x;
    sh[t] = (t < NB_SCAN) ? g_part[t] : 0;
    __syncthreads();
    for (int d = 1; d < 256; d <<= 1) {
        int v = (t >= d) ? sh[t - d] : 0;
        __syncthreads();
        sh[t] += v;
        __syncthreads();
    }
    g_part[t] = (t == 0) ? 0 : sh[t - 1];   // exclusive
}
__global__ __launch_bounds__(256) void scan3_kernel() {
    __shared__ int sh[256];
    int t = threadIdx.x;
    int idx = blockIdx.x * 256 + t;
    int deg = (idx < N_NODES) ? g_degi[idx] : 0;
    sh[t] = deg;
    __syncthreads();
    for (int d = 1; d < 256; d <<= 1) {
        int v = (t >= d) ? sh[t - d] : 0;
        __syncthreads();
        sh[t] += v;
        __syncthreads();
    }
    if (idx < N_NODES) {
        int rp = g_part[blockIdx.x] + sh[t] - deg;
        g_rowptr[idx] = rp;
        g_cursor[idx] = rp;
        g_dinv[idx]   = rsqrtf((float)deg + 1.0f);   // +1 self-loop
    }
}
__global__ void fill_kernel() {
    int e = blockIdx.x * blockDim.x + threadIdx.x;
    if (e >= N_EDGES) return;
    int src = g_src[e];
    int dst = g_dst[e];
    int pos = atomicAdd(&g_cursor[dst], 1);
    g_csr_src[pos] = src;
    g_csr_nrm[pos] = g_dinv[src] * g_dinv[dst];
}

// ---------------- combine: Wc = W_in@W1 (split hi/lo, transposed), wb = b_in@W1
__global__ __launch_bounds__(256)
void combine_kernel(const float* __restrict__ W0, const float* __restrict__ W1,
                    const float* __restrict__ b_in) {
    const int j = threadIdx.x;
    const int p = blockIdx.x;
    float acc = 0.0f;
    if (p < IN_DIM) {
#pragma unroll 8
        for (int k = 0; k < HIDDEN; k++)
            acc += W0[p * HIDDEN + k] * W1[k * HIDDEN + j];
        __nv_bfloat16 hi = __float2bfloat16(acc);
        g_wchi[j * IN_DIM + p] = hi;
        g_wclo[j * IN_DIM + p] = __float2bfloat16(acc - __bfloat162float(hi));
    } else {
#pragma unroll 8
        for (int k = 0; k < HIDDEN; k++)
            acc += b_in[k] * W1[k * HIDDEN + j];
        g_wb[j] = acc;
    }
}
__global__ void prep_w2_kernel(const float* __restrict__ W2) {
    int idx = blockIdx.x * blockDim.x + threadIdx.x;
    if (idx >= HIDDEN * HIDDEN) return;
    int n = idx >> 8, k = idx & 255;
    float v = W2[k * HIDDEN + n];
    __nv_bfloat16 hi = __float2bfloat16(v);
    g_w2hi[n * HIDDEN + k] = hi;
    g_w2lo[n * HIDDEN + k] = __float2bfloat16(v - __bfloat162float(hi));
}

// ---------------- CSR gather: out[n] = sum h[src]*norm + h[n]*dinv^2 ----------
template<int DIM, bool RELU, bool COEF>
__global__ __launch_bounds__(64)
void gather_kernel(const float* __restrict__ ext, int srcSel, int dstSel) {
    const float* __restrict__ h = (srcSel == 0) ? ext : g_bufA;
    float* __restrict__ out = (dstSel == 2) ? g_bufB : g_bufC;

    const int node = blockIdx.x;
    const int tid = threadIdx.x;

    __shared__ int   s_src[64];
    __shared__ float s_nrm[64];

    const float d = g_dinv[node];
    const float d2 = d * d;
    const int beg = g_rowptr[node];
    const int end = beg + g_degi[node];
    float ssum = 0.0f;

    if (DIM == 128) {
        const int c2 = tid * 2;
        float2 self = *(const float2*)(h + (size_t)node * DIM + c2);
        if (RELU) { self.x = fmaxf(self.x, 0.f); self.y = fmaxf(self.y, 0.f); }
        float2 acc = make_float2(self.x * d2, self.y * d2);
        for (int off = beg; off < end; off += 64) {
            int i = off + tid;
            if (i < end) { s_src[tid] = g_csr_src[i]; s_nrm[tid] = g_csr_nrm[i]; }
            __syncthreads();
            int m = min(64, end - off);
#pragma unroll 4
            for (int j = 0; j < m; j++) {
                int s = s_src[j];
                float nm = s_nrm[j];
                ssum += nm;
                float2 v = *(const float2*)(h + (size_t)s * DIM + c2);
                if (RELU) { v.x = fmaxf(v.x, 0.f); v.y = fmaxf(v.y, 0.f); }
                acc.x += v.x * nm; acc.y += v.y * nm;
            }
            __syncthreads();
        }
        *(float2*)(out + (size_t)node * DIM + c2) = acc;
    } else {
        const int c4 = tid * 4;
        float4 self = *(const float4*)(h + (size_t)node * DIM + c4);
        if (RELU) {
            self.x = fmaxf(self.x, 0.f); self.y = fmaxf(self.y, 0.f);
            self.z = fmaxf(self.z, 0.f); self.w = fmaxf(self.w, 0.f);
        }
        float4 acc = make_float4(self.x * d2, self.y * d2, self.z * d2, self.w * d2);
        for (int off = beg; off < end; off += 64) {
            int i = off + tid;
            if (i < end) { s_src[tid] = g_csr_src[i]; s_nrm[tid] = g_csr_nrm[i]; }
            __syncthreads();
            int m = min(64, end - off);
#pragma unroll 4
            for (int j = 0; j < m; j++) {
                int s = s_src[j];
                float nm = s_nrm[j];
                ssum += nm;
                float4 v = *(const float4*)(h + (size_t)s * DIM + c4);
                if (RELU) {
                    v.x = fmaxf(v.x, 0.f); v.y = fmaxf(v.y, 0.f);
                    v.z = fmaxf(v.z, 0.f); v.w = fmaxf(v.w, 0.f);
                }
                acc.x += v.x * nm; acc.y += v.y * nm;
                acc.z += v.z * nm; acc.w += v.w * nm;
            }
            __syncthreads();
        }
        *(float4*)(out + (size_t)node * DIM + c4) = acc;
    }
    if (COEF && tid == 0) g_coef[node] = ssum + d2;
}

// ---------------- mma.sync helper ---------------------------------------------
__device__ __forceinline__ void mma16816(float* c, const uint32_t* a,
                                         uint32_t b0, uint32_t b1) {
    asm volatile(
        "mma.sync.aligned.m16n8k16.row.col.f32.bf16.bf16.f32 "
        "{%0,%1,%2,%3}, {%4,%5,%6,%7}, {%8,%9}, {%0,%1,%2,%3};"
        : "+f"(c[0]), "+f"(c[1]), "+f"(c[2]), "+f"(c[3])
        : "r"(a[0]), "r"(a[1]), "r"(a[2]), "r"(a[3]), "r"(b0), "r"(b1));
}

#define TROW 72
#define T_BYTES (128 * TROW * 2)
#define AH_OFF 0
#define AL_OFF T_BYTES
#define BH_OFF (2 * T_BYTES)
#define BL_OFF (3 * T_BYTES)
#define SMEM_TOTAL (4 * T_BYTES)       // 73728

// ---------------- tensor-core GEMM: C[N,256] = split(A)[N,K] @ W[K,256] -------
template<int K>
__global__ __launch_bounds__(256, 2)
void gemm_mma_kernel(int srcSel, int wSel, int dstSel,
                     const float* __restrict__ bias, int useWb) {
    extern __shared__ char smem[];
    const float* __restrict__ Afp = (srcSel == 1) ? g_bufC : g_bufB;
    const __nv_bfloat16* __restrict__ Wh = (wSel == 0) ? g_wchi : g_w2hi;
    const __nv_bfloat16* __restrict__ Wl = (wSel == 0) ? g_wclo : g_w2lo;
    float* __restrict__ C = (dstSel == 1) ? g_bufA : g_bufC;

    unsigned short* sAh = (unsigned short*)(smem + AH_OFF);
    unsigned short* sAl = (unsigned short*)(smem + AL_OFF);
    unsigned short* sBh = (unsigned short*)(smem + BH_OFF);
    unsigned short* sBl = (unsigned short*)(smem + BL_OFF);

    const int tid = threadIdx.x;
    const int wid = tid >> 5;
    const int lane = tid & 31;
    const int gid = lane >> 2;
    const int tig = lane & 3;
    const int rowBase = blockIdx.x * 128;
    const int colBase = blockIdx.y * 128;
    const int warp_m = (wid & 3) * 32;
    const int warp_n = (wid >> 2) * 64;

    float acc[2][8][4];
#pragma unroll
    for (int mt = 0; mt < 2; mt++)
#pragma unroll
        for (int nt = 0; nt < 8; nt++)
#pragma unroll
            for (int q = 0; q < 4; q++) acc[mt][nt][q] = 0.0f;

    const int NC = K / 64;
    for (int kc = 0; kc < NC; kc++) {
        const int k0 = kc * 64;
        for (int i = tid; i < 1024; i += 256) {
            int r = i >> 3, kg = (i & 7) * 8;
            int gr = rowBase + r;
            if (gr >= N_NODES) gr = N_NODES - 1;   // clamp; tail masked at store
            const float* src = Afp + (size_t)gr * K + k0 + kg;
            float4 v0 = *(const float4*)src;
            float4 v1 = *(const float4*)(src + 4);
            float f[8] = {v0.x, v0.y, v0.z, v0.w, v1.x, v1.y, v1.z, v1.w};
            uint32_t hi[4], lo[4];
#pragma unroll
            for (int q = 0; q < 4; q++) {
                float2 p = make_float2(f[2 * q], f[2 * q + 1]);
                __nv_bfloat162 h2 = __float22bfloat162_rn(p);
                float2 hf = __bfloat1622float2(h2);
                __nv_bfloat162 l2 = __float22bfloat162_rn(
                    make_float2(p.x - hf.x, p.y - hf.y));
                hi[q] = *(uint32_t*)&h2;
                lo[q] = *(uint32_t*)&l2;
            }
            *(uint4*)(sAh + r * TROW + kg) = *(uint4*)hi;
            *(uint4*)(sAl + r * TROW + kg) = *(uint4*)lo;
        }
        for (int i = tid; i < 1024; i += 256) {
            int r = i >> 3, kg = (i & 7) * 8;
            size_t goff = (size_t)(colBase + r) * K + k0 + kg;
            *(float4*)(sBh + r * TROW + kg) = *(const float4*)(Wh + goff);
            *(float4*)(sBl + r * TROW + kg) = *(const float4*)(Wl + goff);
        }
        __syncthreads();

#pragma unroll
        for (int kk = 0; kk < 64; kk += 16) {
            uint32_t ah[2][4], al[2][4];
#pragma unroll
            for (int mt = 0; mt < 2; mt++) {
                const unsigned short* base =
                    sAh + (warp_m + mt * 16 + gid) * TROW + kk + tig * 2;
                ah[mt][0] = *(const uint32_t*)(base);
                ah[mt][1] = *(const uint32_t*)(base + 8 * TROW);
                ah[mt][2] = *(const uint32_t*)(base + 8);
                ah[mt][3] = *(const uint32_t*)(base + 8 * TROW + 8);
                const unsigned short* basl =
                    sAl + (warp_m + mt * 16 + gid) * TROW + kk + tig * 2;
                al[mt][0] = *(const uint32_t*)(basl);
                al[mt][1] = *(const uint32_t*)(basl + 8 * TROW);
                al[mt][2] = *(const uint32_t*)(basl + 8);
                al[mt][3] = *(const uint32_t*)(basl + 8 * TROW + 8);
            }
#pragma unroll
            for (int nt = 0; nt < 8; nt++) {
                const unsigned short* bb =
                    sBh + (warp_n + nt * 8 + gid) * TROW + kk + tig * 2;
                uint32_t b0 = *(const uint32_t*)(bb);
                uint32_t b1 = *(const uint32_t*)(bb + 8);
                const unsigned short* bl =
                    sBl + (warp_n + nt * 8 + gid) * TROW + kk + tig * 2;
                uint32_t l0 = *(const uint32_t*)(bl);
                uint32_t l1 = *(const uint32_t*)(bl + 8);
#pragma unroll
                for (int mt = 0; mt < 2; mt++) {
                    mma16816(acc[mt][nt], ah[mt], b0, b1);
                    mma16816(acc[mt][nt], al[mt], b0, b1);
                    mma16816(acc[mt][nt], ah[mt], l0, l1);
                }
            }
        }
        __syncthreads();
    }

#pragma unroll
    for (int mt = 0; mt < 2; mt++) {
#pragma unroll
        for (int nt = 0; nt < 8; nt++) {
            int r0 = rowBase + warp_m + mt * 16 + gid;
            int cc = colBase + warp_n + nt * 8 + tig * 2;
            float bx = bias[cc], by = bias[cc + 1];
            float w0 = 0.f, w1v = 0.f;
            if (useWb) { w0 = g_wb[cc]; w1v = g_wb[cc + 1]; }
            if (r0 < N_NODES) {
                float cf = useWb ? g_coef[r0] : 0.f;
                float2 v = make_float2(acc[mt][nt][0] + bx + cf * w0,
                                       acc[mt][nt][1] + by + cf * w1v);
                *(float2*)(C + (size_t)r0 * HIDDEN + cc) = v;
            }
            if (r0 + 8 < N_NODES) {
                float cf = useWb ? g_coef[r0 + 8] : 0.f;
                float2 v = make_float2(acc[mt][nt][2] + bx + cf * w0,
                                       acc[mt][nt][3] + by + cf * w1v);
                *(float2*)(C + (size_t)(r0 + 8) * HIDDEN + cc) = v;
            }
        }
    }
}

// ---------------- fused pool + output GEMM ------------------------------------
// block g: sums relu(g_bufC) rows of graph g per column, then 16 threads
// compute out[g] = (pooled/cnt) @ Wout + bout.
__global__ __launch_bounds__(256)
void poolout_kernel(const float* __restrict__ Wout, const float* __restrict__ bout,
                    float* __restrict__ out) {
    __shared__ int s_lo, s_hi;
    __shared__ float s_acc[256];
    const int g = blockIdx.x;
    if (threadIdx.x == 0) {
        int lo = 0, hi = N_NODES;
        while (lo < hi) { int mid = (lo + hi) >> 1; if (g_batch[mid] < g) lo = mid + 1; else hi = mid; }
        s_lo = lo;
        int lo2 = lo, hi2 = N_NODES;
        while (lo2 < hi2) { int mid = (lo2 + hi2) >> 1; if (g_batch[mid] < g + 1) lo2 = mid + 1; else hi2 = mid; }
        s_hi = lo2;
    }
    __syncthreads();
    const int c = threadIdx.x;
    const int lo = s_lo, hi = s_hi;
    float acc = 0.0f;
#pragma unroll 4
    for (int n = lo; n < hi; n++)
        acc += fmaxf(g_bufC[(size_t)n * HIDDEN + c], 0.0f);
    s_acc[c] = acc;
    __syncthreads();
    if (threadIdx.x < N_CLASSES) {
        float inv = 1.0f / fmaxf((float)(hi - lo), 1.0f);
        float o = 0.0f;
#pragma unroll 8
        for (int k = 0; k < HIDDEN; k++)
            o += s_acc[k] * Wout[k * N_CLASSES + threadIdx.x];
        out[g * N_CLASSES + threadIdx.x] = o * inv + bout[threadIdx.x];
    }
}

// ---------------- launch ------------------------------------------------------
extern "C" void kernel_launch(void* const* d_in, const int* in_sizes, int n_in,
                              void* d_out, int out_size) {
    const float* x    = (const float*)d_in[0];
    const void*  ei   = d_in[1];
    const void*  bat  = d_in[2];
    const float* W_in = (const float*)d_in[3];
    const float* b_in = (const float*)d_in[4];
    const float* W1   = (const float*)d_in[5];
    const float* b1   = (const float*)d_in[6];
    const float* W2   = (const float*)d_in[7];
    const float* b2   = (const float*)d_in[8];
    const float* Wout = (const float*)d_in[9];
    const float* bout = (const float*)d_in[10];
    float* out = (float*)d_out;

    const int TPB = 256;
    dim3 gemmGrid((N_NODES + 127) / 128, 2);   // 391 x 2

    cudaFuncSetAttribute(gemm_mma_kernel<IN_DIM>,
                         cudaFuncAttributeMaxDynamicSharedMemorySize, SMEM_TOTAL);
    cudaFuncSetAttribute(gemm_mma_kernel<HIDDEN>,
                         cudaFuncAttributeMaxDynamicSharedMemorySize, SMEM_TOTAL);

    // 1-3: dtype normalize (batch conv zeroes degrees; edges conv counts them)
    detect_kernel<<<1, 1>>>(ei);
    convert_batch_kernel<<<(N_NODES + TPB - 1) / TPB, TPB>>>(bat);
    convert_edges_kernel<<<(N_EDGES + TPB - 1) / TPB, TPB>>>(ei);

    // 4-7: CSR build (3-phase scan + fill)
    scan1_kernel<<<NB_SCAN, 256>>>();
    scan2_kernel<<<1, 256>>>();
    scan3_kernel<<<NB_SCAN, 256>>>();
    fill_kernel<<<(N_EDGES + TPB - 1) / TPB, TPB>>>();

    // 8-9: weight prep
    combine_kernel<<<IN_DIM + 1, 256>>>(W_in, W1, b_in);
    prep_w2_kernel<<<(HIDDEN * HIDDEN + TPB - 1) / TPB, TPB>>>(W2);

    // 10: v = M(x) (128-dim gather) -> bufC, coef
    gather_kernel<IN_DIM, false, true><<<N_NODES, 64>>>(x, 0, 3);

    // 11: C1 = v@Wc + coef*wb + b1 -> bufA   (layer-1 fused GEMM, K=128)
    gemm_mma_kernel<IN_DIM><<<gemmGrid, TPB, SMEM_TOTAL>>>(1, 0, 1, b1, 1);

    // 12: M(relu(C1)) (256-dim gather) -> bufB
    gather_kernel<HIDDEN, true, false><<<N_NODES, 64>>>(nullptr, 1, 2);

    // 13: C2 = M@W2 + b2 -> bufC   (layer-2 GEMM, K=256)
    gemm_mma_kernel<HIDDEN><<<gemmGrid, TPB, SMEM_TOTAL>>>(2, 1, 3, b2, 0);

    // 14: fused pool (relu) + output GEMM
    poolout_kernel<<<N_GRAPHS, TPB>>>(Wout, bout, out);
}